// round 10
// baseline (speedup 1.0000x reference)
#include <cuda_runtime.h>
#include <cuda_bf16.h>
#include <cuda_fp8.h>
#include <cstdint>

#define T_ 4
#define B_ 64
#define D_ 512
#define V_ 256
#define Z_ (T_*B_)            // 256
#define PLANE (B_*D_*V_)
#define TOTAL (Z_*D_*V_)      // 33554432

// ---------------- scratch ----------------
__device__ __nv_bfloat16 g_xb[TOTAL];     // x bf16, native [z][d][v]
__device__ __nv_bfloat16 g_qpre[TOTAL];   // [z][o][v]
__device__ __nv_bfloat16 g_kpre[TOTAL];   // [z][o][v]
__device__ uint8_t       g_sp8[TOTAL];    // gate*k spikes e4m3, [z][v][d]
__device__ __nv_bfloat16 g_wq[D_*D_];
__device__ __nv_bfloat16 g_wk[D_*D_];
__device__ uint8_t       g_wp8[D_*D_];    // Wp e4m3 [o][d]

// ---------------- helpers ----------------
__device__ __forceinline__ uint32_t smem_u32(const void* p) {
    uint32_t a;
    asm("{ .reg .u64 t; cvta.to.shared.u64 t, %1; cvt.u32.u64 %0, t; }" : "=r"(a) : "l"(p));
    return a;
}
__device__ __forceinline__ void cp16(uint32_t sdst, const void* gsrc) {
    asm volatile("cp.async.cg.shared.global [%0], [%1], 16;" :: "r"(sdst), "l"(gsrc) : "memory");
}
#define CP_COMMIT() asm volatile("cp.async.commit_group;" ::: "memory")
#define CP_WAIT1()  asm volatile("cp.async.wait_group 1;" ::: "memory")
#define CP_WAIT0()  asm volatile("cp.async.wait_group 0;" ::: "memory")

__device__ __forceinline__ void ldsm_x4(uint32_t* r, uint32_t addr) {
    asm volatile("ldmatrix.sync.aligned.m8n8.x4.shared.b16 {%0,%1,%2,%3}, [%4];"
        : "=r"(r[0]), "=r"(r[1]), "=r"(r[2]), "=r"(r[3]) : "r"(addr));
}
__device__ __forceinline__ void ldsm_x4_t(uint32_t* r, uint32_t addr) {
    asm volatile("ldmatrix.sync.aligned.m8n8.x4.trans.shared.b16 {%0,%1,%2,%3}, [%4];"
        : "=r"(r[0]), "=r"(r[1]), "=r"(r[2]), "=r"(r[3]) : "r"(addr));
}
__device__ __forceinline__ void mma_bf16(float* d, const uint32_t* a, uint32_t b0, uint32_t b1) {
    asm volatile("mma.sync.aligned.m16n8k16.row.col.f32.bf16.bf16.f32 "
        "{%0,%1,%2,%3}, {%4,%5,%6,%7}, {%8,%9}, {%0,%1,%2,%3};"
        : "+f"(d[0]), "+f"(d[1]), "+f"(d[2]), "+f"(d[3])
        : "r"(a[0]), "r"(a[1]), "r"(a[2]), "r"(a[3]), "r"(b0), "r"(b1));
}
__device__ __forceinline__ void mma_fp8(float* d, const uint32_t* a, uint32_t b0, uint32_t b1) {
    asm volatile("mma.sync.aligned.m16n8k32.row.col.f32.e4m3.e4m3.f32 "
        "{%0,%1,%2,%3}, {%4,%5,%6,%7}, {%8,%9}, {%0,%1,%2,%3};"
        : "+f"(d[0]), "+f"(d[1]), "+f"(d[2]), "+f"(d[3])
        : "r"(a[0]), "r"(a[1]), "r"(a[2]), "r"(a[3]), "r"(b0), "r"(b1));
}

// ---------------------------------------------------------------------------
// Stage-1/2 GEMM (bf16) + folded BN. ONE launch covers both Wq and Wk.
// (unchanged from R9 — at the legacy-HMMA ceiling)
// ---------------------------------------------------------------------------
#define A_STG 10240
#define B_STG 8704
#define SMEM_BF16 (3*(A_STG + B_STG))

__global__ void __launch_bounds__(256, 2) gemm_qk_bf16(
    const __nv_bfloat16* __restrict__ Wq_, const __nv_bfloat16* __restrict__ Wk_,
    const __nv_bfloat16* __restrict__ X,
    const float* __restrict__ qg, const float* __restrict__ qb,
    const float* __restrict__ qm, const float* __restrict__ qv,
    const float* __restrict__ kg, const float* __restrict__ kb,
    const float* __restrict__ km, const float* __restrict__ kv,
    __nv_bfloat16* __restrict__ Q, __nv_bfloat16* __restrict__ K)
{
    extern __shared__ __align__(16) char smem[];
    __shared__ float sScale[128], sBias[128];

    const int tid = threadIdx.x, wid = tid >> 5, lane = tid & 31;
    const int z = blockIdx.x;
    const int which = blockIdx.y >> 2;
    const int o0 = (blockIdx.y & 3) * 128;
    const int v0 = blockIdx.z * 128;

    const __nv_bfloat16* W = which ? Wk_ : Wq_;
    const float* gamma = which ? kg : qg;
    const float* beta  = which ? kb : qb;
    const float* mean  = which ? km : qm;
    const float* var   = which ? kv : qv;
    __nv_bfloat16* O   = which ? K : Q;

    const __nv_bfloat16* Wb = W + (size_t)o0 * D_;
    const __nv_bfloat16* Xb = X + (size_t)z * D_ * V_ + v0;

    if (tid < 128) {
        const float inv = gamma[o0 + tid] * rsqrtf(var[o0 + tid] + 1e-5f);
        sScale[tid] = inv;
        sBias[tid]  = beta[o0 + tid] - mean[o0 + tid] * inv;
    }

    const uint32_t sA = smem_u32(smem);
    const uint32_t sB = sA + 3 * A_STG;
    const int wm = wid & 3, wv = wid >> 2;

    float acc[2][8][4];
    #pragma unroll
    for (int i = 0; i < 2; ++i)
        #pragma unroll
        for (int j = 0; j < 8; ++j)
            #pragma unroll
            for (int q = 0; q < 4; ++q) acc[i][j][q] = 0.f;

    auto issue = [&](int s, int kc) {
        const uint32_t ab = sA + s * A_STG;
        const uint32_t bb = sB + s * B_STG;
        #pragma unroll
        for (int i = 0; i < 2; ++i) {
            const int idx = tid + i * 256;
            const int row = idx >> 2, c = idx & 3;
            cp16(ab + row * 80 + c * 16, Wb + (size_t)row * D_ + kc + c * 8);
        }
        #pragma unroll
        for (int i = 0; i < 2; ++i) {
            const int idx = tid + i * 256;
            const int row = idx >> 4, c = idx & 15;
            cp16(bb + row * 272 + c * 16, Xb + (size_t)(kc + row) * V_ + c * 8);
        }
        CP_COMMIT();
    };

    issue(0, 0);
    issue(1, 32);

    #pragma unroll 1
    for (int c = 0; c < 16; ++c) {
        if (c < 15) CP_WAIT1(); else CP_WAIT0();
        __syncthreads();
        if (c < 14) issue((c + 2) % 3, (c + 2) * 32);

        const int s = c % 3;
        const uint32_t aB = sA + s * A_STG;
        const uint32_t bB = sB + s * B_STG;

        #pragma unroll
        for (int kk = 0; kk < 2; ++kk) {
            uint32_t af[2][4];
            #pragma unroll
            for (int mt = 0; mt < 2; ++mt) {
                const int row = wm * 32 + mt * 16 + (lane & 15);
                ldsm_x4(af[mt], aB + row * 80 + kk * 32 + (lane >> 4) * 16);
            }
            uint32_t bfr[4][4];
            const int sub = lane >> 3;
            const int krow = kk * 16 + (sub & 1) * 8 + (lane & 7);
            #pragma unroll
            for (int g = 0; g < 4; ++g) {
                const int ncol = wv * 64 + g * 16 + (sub >> 1) * 8;
                ldsm_x4_t(bfr[g], bB + krow * 272 + ncol * 2);
            }
            #pragma unroll
            for (int mt = 0; mt < 2; ++mt)
                #pragma unroll
                for (int g = 0; g < 4; ++g) {
                    mma_bf16(acc[mt][g * 2 + 0], af[mt], bfr[g][0], bfr[g][1]);
                    mma_bf16(acc[mt][g * 2 + 1], af[mt], bfr[g][2], bfr[g][3]);
                }
        }
    }

    #pragma unroll
    for (int mt = 0; mt < 2; ++mt) {
        const int oL = wm * 32 + mt * 16 + (lane >> 2);
        #pragma unroll
        for (int h = 0; h < 2; ++h) {
            const int o = oL + h * 8;
            const float sc = sScale[o], bi = sBias[o];
            __nv_bfloat16* orow = O + ((size_t)z * D_ + o0 + o) * V_ + v0;
            #pragma unroll
            for (int nt = 0; nt < 8; ++nt) {
                const int v = wv * 64 + nt * 8 + (lane & 3) * 2;
                const float fa = acc[mt][nt][2 * h]     * sc + bi;
                const float fb = acc[mt][nt][2 * h + 1] * sc + bi;
                const __nv_bfloat162 h2 = __floats2bfloat162_rn(fa, fb);
                *(uint32_t*)(orow + v) = *(const uint32_t*)&h2;
            }
        }
    }
}

// ---------------------------------------------------------------------------
// Fused stage-3: fp8 GEMM + BN + final LIF -> d_out fp32.
// NEW geometry: CTA 128(o) x 128(v), warp tile 32x64 (32 MMAs/chunk/warp —
// same density as the bf16 kernel). A-resident (80KB), continuous 32-chunk
// B pipeline across t, LIF membranes in registers. 1 CTA/SM, 255-reg budget.
// ---------------------------------------------------------------------------
#define FA_CHUNK 10240                   // 128 rows * 80 B
#define FA_TOTAL (8*FA_CHUNK)            // 81920
#define FB_STG 10240                     // 128 v-rows * 80 B
#define SMEM_F (FA_TOTAL + 3*FB_STG)     // 112640

__global__ void __launch_bounds__(256, 1) gemm_fp8_lif(
    const uint8_t* __restrict__ W8,
    const uint8_t* __restrict__ S8,
    const float* __restrict__ gamma, const float* __restrict__ beta,
    const float* __restrict__ mean, const float* __restrict__ var,
    float* __restrict__ out)
{
    extern __shared__ __align__(16) char smem[];
    __shared__ float sScale[128], sBias[128];

    const int tid = threadIdx.x, wid = tid >> 5, lane = tid & 31;
    const int b = blockIdx.x, o0 = blockIdx.y * 128, v0 = blockIdx.z * 128;

    const uint8_t* Ab = W8 + (size_t)o0 * D_;

    if (tid < 128) {
        const float inv = gamma[o0 + tid] * rsqrtf(var[o0 + tid] + 1e-5f);
        sScale[tid] = inv;
        sBias[tid]  = beta[o0 + tid] - mean[o0 + tid] * inv;
    }

    const uint32_t sA = smem_u32(smem);
    const uint32_t sB = sA + FA_TOTAL;
    const int wm = wid & 3, wv = wid >> 2;

    // Preload entire A (Wp tile) once: 8 chunks x 128 rows x 64 B (pitch 80).
    #pragma unroll
    for (int i = 0; i < 16; ++i) {
        const int idx = tid + i * 256;        // 0..4095
        const int kc = idx >> 9;
        const int rem = idx & 511;
        const int row = rem >> 2, cc = rem & 3;
        cp16(sA + kc * FA_CHUNK + row * 80 + cc * 16,
             Ab + (size_t)row * D_ + kc * 64 + cc * 16);
    }
    CP_COMMIT();

    // B chunk j (0..31): t = j>>3, k-chunk = j&7. 128 v-rows x 4 x 16B.
    auto issueB = [&](int s, int j) {
        const int t = j >> 3, kc = (j & 7) * 64;
        const uint8_t* Bb = S8 + ((size_t)(t * B_ + b) * V_ + v0) * D_;
        #pragma unroll
        for (int i = 0; i < 2; ++i) {
            const int idx = tid + i * 256;
            const int row = idx >> 2, cc = idx & 3;
            cp16(sB + s * FB_STG + row * 80 + cc * 16,
                 Bb + (size_t)row * D_ + kc + cc * 16);
        }
        CP_COMMIT();
    };

    issueB(0, 0);
    issueB(1, 1);
    CP_WAIT0();
    __syncthreads();

    float vm[2][2][8][2];   // membranes [mt][h][nt][pair], persist across t
    #pragma unroll
    for (int i = 0; i < 2; ++i)
        #pragma unroll
        for (int j = 0; j < 2; ++j)
            #pragma unroll
            for (int q = 0; q < 8; ++q) { vm[i][j][q][0] = 0.f; vm[i][j][q][1] = 0.f; }

    float acc[2][8][4];
    #pragma unroll
    for (int i = 0; i < 2; ++i)
        #pragma unroll
        for (int j = 0; j < 8; ++j)
            #pragma unroll
            for (int q = 0; q < 4; ++q) acc[i][j][q] = 0.f;

    #pragma unroll 1
    for (int j = 0; j < 32; ++j) {
        if (j > 0) {
            if (j < 31) CP_WAIT1(); else CP_WAIT0();
        }
        __syncthreads();
        if (j < 30) issueB((j + 2) % 3, j + 2);

        const uint32_t aB = sA + (j & 7) * FA_CHUNK;
        const uint32_t bB = sB + (j % 3) * FB_STG;

        #pragma unroll
        for (int kk = 0; kk < 2; ++kk) {
            uint32_t af[2][4];
            #pragma unroll
            for (int mt = 0; mt < 2; ++mt) {
                const int row = wm * 32 + mt * 16 + (lane & 15);
                ldsm_x4(af[mt], aB + row * 80 + kk * 32 + (lane >> 4) * 16);
            }
            uint32_t bfr[4][4];
            #pragma unroll
            for (int g = 0; g < 4; ++g) {
                const int row = wv * 64 + g * 16 + (lane & 15);
                ldsm_x4(bfr[g], bB + row * 80 + kk * 32 + (lane >> 4) * 16);
            }
            #pragma unroll
            for (int mt = 0; mt < 2; ++mt)
                #pragma unroll
                for (int g = 0; g < 4; ++g) {
                    mma_fp8(acc[mt][g * 2 + 0], af[mt], bfr[g][0], bfr[g][2]);
                    mma_fp8(acc[mt][g * 2 + 1], af[mt], bfr[g][1], bfr[g][3]);
                }
        }

        if ((j & 7) == 7) {
            // end of timestep: BN + LIF + store, reset acc
            const int t = j >> 3;
            const size_t zofs = (size_t)(t * B_ + b) * D_;
            #pragma unroll
            for (int mt = 0; mt < 2; ++mt) {
                const int oL = wm * 32 + mt * 16 + (lane >> 2);
                #pragma unroll
                for (int h = 0; h < 2; ++h) {
                    const int o = oL + h * 8;
                    const float sc = sScale[o], bi = sBias[o];
                    float* orow = out + (zofs + o0 + o) * V_ + v0;
                    #pragma unroll
                    for (int nt = 0; nt < 8; ++nt) {
                        const int v = wv * 64 + nt * 8 + (lane & 3) * 2;
                        const float f0 = acc[mt][nt][2 * h]     * sc + bi;
                        const float f1 = acc[mt][nt][2 * h + 1] * sc + bi;
                        float m0 = (vm[mt][h][nt][0] + f0) * 0.5f;
                        float m1 = (vm[mt][h][nt][1] + f1) * 0.5f;
                        const float s0 = (m0 >= 1.f) ? 1.f : 0.f;
                        const float s1 = (m1 >= 1.f) ? 1.f : 0.f;
                        vm[mt][h][nt][0] = m0 * (1.f - s0);
                        vm[mt][h][nt][1] = m1 * (1.f - s1);
                        *(float2*)(orow + v) = make_float2(s0, s1);
                        acc[mt][nt][2 * h] = 0.f;
                        acc[mt][nt][2 * h + 1] = 0.f;
                    }
                }
            }
        }
    }
}

// ---------------------------------------------------------------------------
// Single converter launch (unchanged from R9).
// ---------------------------------------------------------------------------
#define XBLOCKS (TOTAL / 1024)
#define WBLOCKS (D_ * D_ / 256)

__global__ void convert_all_kernel(
    const float* __restrict__ x, __nv_bfloat16* __restrict__ xb,
    const float* __restrict__ wq, const float* __restrict__ wk,
    const float* __restrict__ wp,
    __nv_bfloat16* __restrict__ dq, __nv_bfloat16* __restrict__ dk,
    uint8_t* __restrict__ dp)
{
    if (blockIdx.x < XBLOCKS) {
        const size_t i = (size_t)blockIdx.x * 256 + threadIdx.x;
        const float4 f = ((const float4*)x)[i];
        const __nv_bfloat162 a = __floats2bfloat162_rn(f.x, f.y);
        const __nv_bfloat162 b = __floats2bfloat162_rn(f.z, f.w);
        uint2 u;
        u.x = *(const uint32_t*)&a;
        u.y = *(const uint32_t*)&b;
        ((uint2*)xb)[i] = u;
    } else {
        const int i = (blockIdx.x - XBLOCKS) * 256 + threadIdx.x;
        dq[i] = __float2bfloat16(wq[i]);
        dk[i] = __float2bfloat16(wk[i]);
        dp[i] = (uint8_t)__nv_cvt_float_to_fp8(wp[i], __NV_SATFINITE, __NV_E4M3);
    }
}

// ---------------------------------------------------------------------------
// lif_gate (unchanged from R9).
// ---------------------------------------------------------------------------
__global__ void __launch_bounds__(512, 2) lif_gate_kernel(
    const __nv_bfloat16* __restrict__ q,
    const __nv_bfloat16* __restrict__ k,
    uint8_t* __restrict__ sp8)
{
    __shared__ float part[4][4][128];
    __shared__ uint8_t gate8[4][128];

    const int b = blockIdx.x, h = blockIdx.y;
    const int tid = threadIdx.x;
    const int c = tid >> 7, vloc = tid & 127;
    const int v = blockIdx.z * 128 + vloc;
    const int d0 = h * 128 + c * 32;

#define IDX(t, d) ((((size_t)((t) * B_ + b)) * D_ + (d)) * V_ + v)
    float qs0 = 0.f, qs1 = 0.f, qs2 = 0.f, qs3 = 0.f;
    #pragma unroll 4
    for (int j = 0; j < 32; ++j) {
        const int d = d0 + j;
        float vmq = 0.f, s;
        vmq = (vmq + __bfloat162float(q[IDX(0, d)])) * 0.5f;
        s = (vmq >= 1.f) ? 1.f : 0.f; qs0 += s; vmq *= (1.f - s);
        vmq = (vmq + __bfloat162float(q[IDX(1, d)])) * 0.5f;
        s = (vmq >= 1.f) ? 1.f : 0.f; qs1 += s; vmq *= (1.f - s);
        vmq = (vmq + __bfloat162float(q[IDX(2, d)])) * 0.5f;
        s = (vmq >= 1.f) ? 1.f : 0.f; qs2 += s; vmq *= (1.f - s);
        vmq = (vmq + __bfloat162float(q[IDX(3, d)])) * 0.5f;
        s = (vmq >= 1.f) ? 1.f : 0.f; qs3 += s;
    }
    part[c][0][vloc] = qs0; part[c][1][vloc] = qs1;
    part[c][2][vloc] = qs2; part[c][3][vloc] = qs3;
    __syncthreads();

    if (c == 0) {
        float vg = 0.f;
        #pragma unroll
        for (int t = 0; t < 4; ++t) {
            const float tot = part[0][t][vloc] + part[1][t][vloc]
                            + part[2][t][vloc] + part[3][t][vloc];
            vg = (vg + tot) * 0.5f;
            const float g = (vg >= 0.5f) ? 1.f : 0.f;
            gate8[t][vloc] = (g != 0.f) ? 0x38 : 0x00;
            vg *= (1.f - g);
        }
    }
    __syncthreads();

    const uint8_t gb0 = gate8[0][vloc], gb1 = gate8[1][vloc];
    const uint8_t gb2 = gate8[2][vloc], gb3 = gate8[3][vloc];

    #pragma unroll
    for (int half = 0; half < 2; ++half) {
        uint32_t w0[4] = {0,0,0,0}, w1[4] = {0,0,0,0}, w2[4] = {0,0,0,0}, w3[4] = {0,0,0,0};
        #pragma unroll
        for (int j = 0; j < 16; ++j) {
            const int d = d0 + half * 16 + j;
            const int wi = j >> 2, sh = (j & 3) * 8;
            float vmk = 0.f, s;
            vmk = (vmk + __bfloat162float(k[IDX(0, d)])) * 0.5f;
            s = (vmk >= 1.f) ? 1.f : 0.f;
            if (s != 0.f) w0[wi] |= (uint32_t)gb0 << sh;
            vmk *= (1.f - s);
            vmk = (vmk + __bfloat162float(k[IDX(1, d)])) * 0.5f;
            s = (vmk >= 1.f) ? 1.f : 0.f;
            if (s != 0.f) w1[wi] |= (uint32_t)gb1 << sh;
            vmk *= (1.f - s);
            vmk = (vmk + __bfloat162float(k[IDX(2, d)])) * 0.5f;
            s = (vmk >= 1.f) ? 1.f : 0.f;
            if (s != 0.f) w2[wi] |= (uint32_t)gb2 << sh;
            vmk *= (1.f - s);
            vmk = (vmk + __bfloat162float(k[IDX(3, d)])) * 0.5f;
            s = (vmk >= 1.f) ? 1.f : 0.f;
            if (s != 0.f) w3[wi] |= (uint32_t)gb3 << sh;
        }
        const size_t base = (size_t)v * D_ + d0 + half * 16;
        *(uint4*)(sp8 + (size_t)(0 * B_ + b) * V_ * D_ + base) = make_uint4(w0[0], w0[1], w0[2], w0[3]);
        *(uint4*)(sp8 + (size_t)(1 * B_ + b) * V_ * D_ + base) = make_uint4(w1[0], w1[1], w1[2], w1[3]);
        *(uint4*)(sp8 + (size_t)(2 * B_ + b) * V_ * D_ + base) = make_uint4(w2[0], w2[1], w2[2], w2[3]);
        *(uint4*)(sp8 + (size_t)(3 * B_ + b) * V_ * D_ + base) = make_uint4(w3[0], w3[1], w3[2], w3[3]);
    }
#undef IDX
}

// ---------------------------------------------------------------------------
extern "C" void kernel_launch(void* const* d_in, const int* in_sizes, int n_in,
                              void* d_out, int out_size) {
    const float* x  = (const float*)d_in[0];
    const float* Wq = (const float*)d_in[1];
    const float* qg = (const float*)d_in[2];
    const float* qb = (const float*)d_in[3];
    const float* qm = (const float*)d_in[4];
    const float* qv = (const float*)d_in[5];
    const float* Wk = (const float*)d_in[6];
    const float* kg = (const float*)d_in[7];
    const float* kb = (const float*)d_in[8];
    const float* km = (const float*)d_in[9];
    const float* kv = (const float*)d_in[10];
    const float* Wp = (const float*)d_in[11];
    const float* pg = (const float*)d_in[12];
    const float* pb = (const float*)d_in[13];
    const float* pm = (const float*)d_in[14];
    const float* pv = (const float*)d_in[15];
    float* out = (float*)d_out;

    __nv_bfloat16 *xb, *qp, *kp, *wq, *wk;
    uint8_t *sp8, *wp8;
    cudaGetSymbolAddress((void**)&xb, g_xb);
    cudaGetSymbolAddress((void**)&qp, g_qpre);
    cudaGetSymbolAddress((void**)&kp, g_kpre);
    cudaGetSymbolAddress((void**)&sp8, g_sp8);
    cudaGetSymbolAddress((void**)&wq, g_wq);
    cudaGetSymbolAddress((void**)&wk, g_wk);
    cudaGetSymbolAddress((void**)&wp8, g_wp8);

    cudaFuncSetAttribute(gemm_qk_bf16, cudaFuncAttributeMaxDynamicSharedMemorySize, SMEM_BF16);
    cudaFuncSetAttribute(gemm_fp8_lif, cudaFuncAttributeMaxDynamicSharedMemorySize, SMEM_F);

    convert_all_kernel<<<XBLOCKS + WBLOCKS, 256>>>(x, xb, Wq, Wk, Wp, wq, wk, wp8);

    gemm_qk_bf16<<<dim3(Z_, 8, 2), 256, SMEM_BF16>>>(
        wq, wk, xb, qg, qb, qm, qv, kg, kb, km, kv, qp, kp);
    lif_gate_kernel<<<dim3(B_, 4, 2), 512>>>(qp, kp, sp8);
    gemm_fp8_lif<<<dim3(B_, D_ / 128, V_ / 128), 256, SMEM_F>>>(
        wp8, sp8, pg, pb, pm, pv, out);
}

// round 11
// speedup vs baseline: 1.0049x; 1.0049x over previous
#include <cuda_runtime.h>
#include <cuda_bf16.h>
#include <cuda_fp8.h>
#include <cstdint>

#define T_ 4
#define B_ 64
#define D_ 512
#define V_ 256
#define Z_ (T_*B_)            // 256
#define PLANE (B_*D_*V_)
#define TOTAL (Z_*D_*V_)      // 33554432

// ---------------- scratch ----------------
__device__ __nv_bfloat16 g_xb[TOTAL];     // x bf16, native [z][d][v]
__device__ __nv_bfloat16 g_qpre[TOTAL];   // [z][o][v]
__device__ __nv_bfloat16 g_kpre[TOTAL];   // [z][o][v] (reused for stage-3 pre)
__device__ uint8_t       g_sp8[TOTAL];    // gate*k spikes e4m3, [z][v][d]
__device__ __nv_bfloat16 g_wq[D_*D_];
__device__ __nv_bfloat16 g_wk[D_*D_];
__device__ uint8_t       g_wp8[D_*D_];    // Wp e4m3 [o][d]

// ---------------- helpers ----------------
__device__ __forceinline__ uint32_t smem_u32(const void* p) {
    uint32_t a;
    asm("{ .reg .u64 t; cvta.to.shared.u64 t, %1; cvt.u32.u64 %0, t; }" : "=r"(a) : "l"(p));
    return a;
}
__device__ __forceinline__ void cp16(uint32_t sdst, const void* gsrc) {
    asm volatile("cp.async.cg.shared.global [%0], [%1], 16;" :: "r"(sdst), "l"(gsrc) : "memory");
}
#define CP_COMMIT() asm volatile("cp.async.commit_group;" ::: "memory")
#define CP_WAIT1()  asm volatile("cp.async.wait_group 1;" ::: "memory")
#define CP_WAIT0()  asm volatile("cp.async.wait_group 0;" ::: "memory")

__device__ __forceinline__ void ldsm_x4(uint32_t* r, uint32_t addr) {
    asm volatile("ldmatrix.sync.aligned.m8n8.x4.shared.b16 {%0,%1,%2,%3}, [%4];"
        : "=r"(r[0]), "=r"(r[1]), "=r"(r[2]), "=r"(r[3]) : "r"(addr));
}
__device__ __forceinline__ void ldsm_x4_t(uint32_t* r, uint32_t addr) {
    asm volatile("ldmatrix.sync.aligned.m8n8.x4.trans.shared.b16 {%0,%1,%2,%3}, [%4];"
        : "=r"(r[0]), "=r"(r[1]), "=r"(r[2]), "=r"(r[3]) : "r"(addr));
}
__device__ __forceinline__ void mma_bf16(float* d, const uint32_t* a, uint32_t b0, uint32_t b1) {
    asm volatile("mma.sync.aligned.m16n8k16.row.col.f32.bf16.bf16.f32 "
        "{%0,%1,%2,%3}, {%4,%5,%6,%7}, {%8,%9}, {%0,%1,%2,%3};"
        : "+f"(d[0]), "+f"(d[1]), "+f"(d[2]), "+f"(d[3])
        : "r"(a[0]), "r"(a[1]), "r"(a[2]), "r"(a[3]), "r"(b0), "r"(b1));
}
__device__ __forceinline__ void mma_fp8(float* d, const uint32_t* a, uint32_t b0, uint32_t b1) {
    asm volatile("mma.sync.aligned.m16n8k32.row.col.f32.e4m3.e4m3.f32 "
        "{%0,%1,%2,%3}, {%4,%5,%6,%7}, {%8,%9}, {%0,%1,%2,%3};"
        : "+f"(d[0]), "+f"(d[1]), "+f"(d[2]), "+f"(d[3])
        : "r"(a[0]), "r"(a[1]), "r"(a[2]), "r"(a[3]), "r"(b0), "r"(b1));
}

// ---------------------------------------------------------------------------
// Stage-1/2 GEMM (bf16) + folded BN. ONE launch covers both Wq and Wk.
// (unchanged from R9 — at the legacy-HMMA ceiling)
// ---------------------------------------------------------------------------
#define A_STG 10240
#define B_STG 8704
#define SMEM_BF16 (3*(A_STG + B_STG))

__global__ void __launch_bounds__(256, 2) gemm_qk_bf16(
    const __nv_bfloat16* __restrict__ Wq_, const __nv_bfloat16* __restrict__ Wk_,
    const __nv_bfloat16* __restrict__ X,
    const float* __restrict__ qg, const float* __restrict__ qb,
    const float* __restrict__ qm, const float* __restrict__ qv,
    const float* __restrict__ kg, const float* __restrict__ kb,
    const float* __restrict__ km, const float* __restrict__ kv,
    __nv_bfloat16* __restrict__ Q, __nv_bfloat16* __restrict__ K)
{
    extern __shared__ __align__(16) char smem[];
    __shared__ float sScale[128], sBias[128];

    const int tid = threadIdx.x, wid = tid >> 5, lane = tid & 31;
    const int z = blockIdx.x;
    const int which = blockIdx.y >> 2;
    const int o0 = (blockIdx.y & 3) * 128;
    const int v0 = blockIdx.z * 128;

    const __nv_bfloat16* W = which ? Wk_ : Wq_;
    const float* gamma = which ? kg : qg;
    const float* beta  = which ? kb : qb;
    const float* mean  = which ? km : qm;
    const float* var   = which ? kv : qv;
    __nv_bfloat16* O   = which ? K : Q;

    const __nv_bfloat16* Wb = W + (size_t)o0 * D_;
    const __nv_bfloat16* Xb = X + (size_t)z * D_ * V_ + v0;

    if (tid < 128) {
        const float inv = gamma[o0 + tid] * rsqrtf(var[o0 + tid] + 1e-5f);
        sScale[tid] = inv;
        sBias[tid]  = beta[o0 + tid] - mean[o0 + tid] * inv;
    }

    const uint32_t sA = smem_u32(smem);
    const uint32_t sB = sA + 3 * A_STG;
    const int wm = wid & 3, wv = wid >> 2;

    float acc[2][8][4];
    #pragma unroll
    for (int i = 0; i < 2; ++i)
        #pragma unroll
        for (int j = 0; j < 8; ++j)
            #pragma unroll
            for (int q = 0; q < 4; ++q) acc[i][j][q] = 0.f;

    auto issue = [&](int s, int kc) {
        const uint32_t ab = sA + s * A_STG;
        const uint32_t bb = sB + s * B_STG;
        #pragma unroll
        for (int i = 0; i < 2; ++i) {
            const int idx = tid + i * 256;
            const int row = idx >> 2, c = idx & 3;
            cp16(ab + row * 80 + c * 16, Wb + (size_t)row * D_ + kc + c * 8);
        }
        #pragma unroll
        for (int i = 0; i < 2; ++i) {
            const int idx = tid + i * 256;
            const int row = idx >> 4, c = idx & 15;
            cp16(bb + row * 272 + c * 16, Xb + (size_t)(kc + row) * V_ + c * 8);
        }
        CP_COMMIT();
    };

    issue(0, 0);
    issue(1, 32);

    #pragma unroll 1
    for (int c = 0; c < 16; ++c) {
        if (c < 15) CP_WAIT1(); else CP_WAIT0();
        __syncthreads();
        if (c < 14) issue((c + 2) % 3, (c + 2) * 32);

        const int s = c % 3;
        const uint32_t aB = sA + s * A_STG;
        const uint32_t bB = sB + s * B_STG;

        #pragma unroll
        for (int kk = 0; kk < 2; ++kk) {
            uint32_t af[2][4];
            #pragma unroll
            for (int mt = 0; mt < 2; ++mt) {
                const int row = wm * 32 + mt * 16 + (lane & 15);
                ldsm_x4(af[mt], aB + row * 80 + kk * 32 + (lane >> 4) * 16);
            }
            uint32_t bfr[4][4];
            const int sub = lane >> 3;
            const int krow = kk * 16 + (sub & 1) * 8 + (lane & 7);
            #pragma unroll
            for (int g = 0; g < 4; ++g) {
                const int ncol = wv * 64 + g * 16 + (sub >> 1) * 8;
                ldsm_x4_t(bfr[g], bB + krow * 272 + ncol * 2);
            }
            #pragma unroll
            for (int mt = 0; mt < 2; ++mt)
                #pragma unroll
                for (int g = 0; g < 4; ++g) {
                    mma_bf16(acc[mt][g * 2 + 0], af[mt], bfr[g][0], bfr[g][1]);
                    mma_bf16(acc[mt][g * 2 + 1], af[mt], bfr[g][2], bfr[g][3]);
                }
        }
    }

    #pragma unroll
    for (int mt = 0; mt < 2; ++mt) {
        const int oL = wm * 32 + mt * 16 + (lane >> 2);
        #pragma unroll
        for (int h = 0; h < 2; ++h) {
            const int o = oL + h * 8;
            const float sc = sScale[o], bi = sBias[o];
            __nv_bfloat16* orow = O + ((size_t)z * D_ + o0 + o) * V_ + v0;
            #pragma unroll
            for (int nt = 0; nt < 8; ++nt) {
                const int v = wv * 64 + nt * 8 + (lane & 3) * 2;
                const float fa = acc[mt][nt][2 * h]     * sc + bi;
                const float fb = acc[mt][nt][2 * h + 1] * sc + bi;
                const __nv_bfloat162 h2 = __floats2bfloat162_rn(fa, fb);
                *(uint32_t*)(orow + v) = *(const uint32_t*)&h2;
            }
        }
    }
}

// ---------------------------------------------------------------------------
// Stage-3 GEMM (fp8 e4m3) + folded BN — R5 version verbatim (measured ~65us):
//   O[z][o][v] = BN_o( sum_d Wp8[o][d] * S8[z][v][d]^T ), bf16 out.
// CTA 128x128, warps 4(o:32) x 2(v:64), K=512 in 8 chunks of 64, 2 CTAs/SM.
// ---------------------------------------------------------------------------
#define F_STG 10240            // 128 rows * 80 B
#define SMEM_FP8 (6*F_STG)     // 61440

__global__ void __launch_bounds__(256, 2) gemm_bn_fp8(
    const uint8_t* __restrict__ W8,
    const uint8_t* __restrict__ S8,
    const float* __restrict__ gamma, const float* __restrict__ beta,
    const float* __restrict__ mean, const float* __restrict__ var,
    __nv_bfloat16* __restrict__ O)
{
    extern __shared__ __align__(16) char smem[];
    __shared__ float sScale[128], sBias[128];

    const int tid = threadIdx.x, wid = tid >> 5, lane = tid & 31;
    const int z = blockIdx.x, o0 = blockIdx.y * 128, v0 = blockIdx.z * 128;

    const uint8_t* Ab = W8 + (size_t)o0 * D_;
    const uint8_t* Bb = S8 + ((size_t)z * V_ + v0) * D_;

    if (tid < 128) {
        const float inv = gamma[o0 + tid] * rsqrtf(var[o0 + tid] + 1e-5f);
        sScale[tid] = inv;
        sBias[tid]  = beta[o0 + tid] - mean[o0 + tid] * inv;
    }

    const uint32_t sA = smem_u32(smem);
    const uint32_t sB = sA + 3 * F_STG;
    const int wm = wid & 3, wv = wid >> 2;

    float acc[2][8][4];
    #pragma unroll
    for (int i = 0; i < 2; ++i)
        #pragma unroll
        for (int j = 0; j < 8; ++j)
            #pragma unroll
            for (int q = 0; q < 4; ++q) acc[i][j][q] = 0.f;

    auto issue = [&](int s, int kc) {
        const uint32_t ab = sA + s * F_STG;
        const uint32_t bb = sB + s * F_STG;
        #pragma unroll
        for (int i = 0; i < 2; ++i) {
            const int idx = tid + i * 256;
            const int row = idx >> 2, c = idx & 3;
            cp16(ab + row * 80 + c * 16, Ab + (size_t)row * D_ + kc + c * 16);
        }
        #pragma unroll
        for (int i = 0; i < 2; ++i) {
            const int idx = tid + i * 256;
            const int row = idx >> 2, c = idx & 3;
            cp16(bb + row * 80 + c * 16, Bb + (size_t)row * D_ + kc + c * 16);
        }
        CP_COMMIT();
    };

    issue(0, 0);
    issue(1, 64);

    #pragma unroll 1
    for (int c = 0; c < 8; ++c) {
        if (c < 7) CP_WAIT1(); else CP_WAIT0();
        __syncthreads();
        if (c < 6) issue((c + 2) % 3, (c + 2) * 64);

        const int s = c % 3;
        const uint32_t aB = sA + s * F_STG;
        const uint32_t bB = sB + s * F_STG;

        #pragma unroll
        for (int kk = 0; kk < 2; ++kk) {
            uint32_t af[2][4];
            #pragma unroll
            for (int mt = 0; mt < 2; ++mt) {
                const int row = wm * 32 + mt * 16 + (lane & 15);
                ldsm_x4(af[mt], aB + row * 80 + kk * 32 + (lane >> 4) * 16);
            }
            uint32_t bfr[4][4];
            #pragma unroll
            for (int g = 0; g < 4; ++g) {
                const int row = wv * 64 + g * 16 + (lane & 15);
                ldsm_x4(bfr[g], bB + row * 80 + kk * 32 + (lane >> 4) * 16);
            }
            #pragma unroll
            for (int mt = 0; mt < 2; ++mt)
                #pragma unroll
                for (int g = 0; g < 4; ++g) {
                    mma_fp8(acc[mt][g * 2 + 0], af[mt], bfr[g][0], bfr[g][2]);
                    mma_fp8(acc[mt][g * 2 + 1], af[mt], bfr[g][1], bfr[g][3]);
                }
        }
    }

    #pragma unroll
    for (int mt = 0; mt < 2; ++mt) {
        const int oL = wm * 32 + mt * 16 + (lane >> 2);
        #pragma unroll
        for (int h = 0; h < 2; ++h) {
            const int o = oL + h * 8;
            const float sc = sScale[o], bi = sBias[o];
            __nv_bfloat16* orow = O + ((size_t)z * D_ + o0 + o) * V_ + v0;
            #pragma unroll
            for (int nt = 0; nt < 8; ++nt) {
                const int v = wv * 64 + nt * 8 + (lane & 3) * 2;
                const float fa = acc[mt][nt][2 * h]     * sc + bi;
                const float fb = acc[mt][nt][2 * h + 1] * sc + bi;
                const __nv_bfloat162 h2 = __floats2bfloat162_rn(fa, fb);
                *(uint32_t*)(orow + v) = *(const uint32_t*)&h2;
            }
        }
    }
}

// ---------------------------------------------------------------------------
// Final LIF(1.0) over t, [z][o][v] bf16 -> d_out [t][b][o][v] fp32 (4-wide).
// ---------------------------------------------------------------------------
__global__ void lif_final_kernel(const __nv_bfloat16* __restrict__ pre, float* __restrict__ out) {
    const size_t i4 = (size_t)blockIdx.x * blockDim.x + threadIdx.x;   // PLANE/4
    float v0 = 0.f, v1 = 0.f, v2 = 0.f, v3 = 0.f;
    #pragma unroll
    for (int t = 0; t < 4; ++t) {
        const uint2 u = ((const uint2*)(pre + (size_t)t * PLANE))[i4];
        const __nv_bfloat162 ha = *(const __nv_bfloat162*)&u.x;
        const __nv_bfloat162 hb = *(const __nv_bfloat162*)&u.y;
        v0 = (v0 + __bfloat162float(ha.x)) * 0.5f;
        v1 = (v1 + __bfloat162float(ha.y)) * 0.5f;
        v2 = (v2 + __bfloat162float(hb.x)) * 0.5f;
        v3 = (v3 + __bfloat162float(hb.y)) * 0.5f;
        const float s0 = (v0 >= 1.f) ? 1.f : 0.f;
        const float s1 = (v1 >= 1.f) ? 1.f : 0.f;
        const float s2 = (v2 >= 1.f) ? 1.f : 0.f;
        const float s3 = (v3 >= 1.f) ? 1.f : 0.f;
        ((float4*)(out + (size_t)t * PLANE))[i4] = make_float4(s0, s1, s2, s3);
        v0 *= (1.f - s0); v1 *= (1.f - s1); v2 *= (1.f - s2); v3 *= (1.f - s3);
    }
}

// ---------------------------------------------------------------------------
// Single converter launch (unchanged from R9).
// ---------------------------------------------------------------------------
#define XBLOCKS (TOTAL / 1024)
#define WBLOCKS (D_ * D_ / 256)

__global__ void convert_all_kernel(
    const float* __restrict__ x, __nv_bfloat16* __restrict__ xb,
    const float* __restrict__ wq, const float* __restrict__ wk,
    const float* __restrict__ wp,
    __nv_bfloat16* __restrict__ dq, __nv_bfloat16* __restrict__ dk,
    uint8_t* __restrict__ dp)
{
    if (blockIdx.x < XBLOCKS) {
        const size_t i = (size_t)blockIdx.x * 256 + threadIdx.x;
        const float4 f = ((const float4*)x)[i];
        const __nv_bfloat162 a = __floats2bfloat162_rn(f.x, f.y);
        const __nv_bfloat162 b = __floats2bfloat162_rn(f.z, f.w);
        uint2 u;
        u.x = *(const uint32_t*)&a;
        u.y = *(const uint32_t*)&b;
        ((uint2*)xb)[i] = u;
    } else {
        const int i = (blockIdx.x - XBLOCKS) * 256 + threadIdx.x;
        dq[i] = __float2bfloat16(wq[i]);
        dk[i] = __float2bfloat16(wk[i]);
        dp[i] = (uint8_t)__nv_cvt_float_to_fp8(wp[i], __NV_SATFINITE, __NV_E4M3);
    }
}

// ---------------------------------------------------------------------------
// lif_gate (unchanged from R9).
// ---------------------------------------------------------------------------
__global__ void __launch_bounds__(512, 2) lif_gate_kernel(
    const __nv_bfloat16* __restrict__ q,
    const __nv_bfloat16* __restrict__ k,
    uint8_t* __restrict__ sp8)
{
    __shared__ float part[4][4][128];
    __shared__ uint8_t gate8[4][128];

    const int b = blockIdx.x, h = blockIdx.y;
    const int tid = threadIdx.x;
    const int c = tid >> 7, vloc = tid & 127;
    const int v = blockIdx.z * 128 + vloc;
    const int d0 = h * 128 + c * 32;

#define IDX(t, d) ((((size_t)((t) * B_ + b)) * D_ + (d)) * V_ + v)
    float qs0 = 0.f, qs1 = 0.f, qs2 = 0.f, qs3 = 0.f;
    #pragma unroll 4
    for (int j = 0; j < 32; ++j) {
        const int d = d0 + j;
        float vmq = 0.f, s;
        vmq = (vmq + __bfloat162float(q[IDX(0, d)])) * 0.5f;
        s = (vmq >= 1.f) ? 1.f : 0.f; qs0 += s; vmq *= (1.f - s);
        vmq = (vmq + __bfloat162float(q[IDX(1, d)])) * 0.5f;
        s = (vmq >= 1.f) ? 1.f : 0.f; qs1 += s; vmq *= (1.f - s);
        vmq = (vmq + __bfloat162float(q[IDX(2, d)])) * 0.5f;
        s = (vmq >= 1.f) ? 1.f : 0.f; qs2 += s; vmq *= (1.f - s);
        vmq = (vmq + __bfloat162float(q[IDX(3, d)])) * 0.5f;
        s = (vmq >= 1.f) ? 1.f : 0.f; qs3 += s;
    }
    part[c][0][vloc] = qs0; part[c][1][vloc] = qs1;
    part[c][2][vloc] = qs2; part[c][3][vloc] = qs3;
    __syncthreads();

    if (c == 0) {
        float vg = 0.f;
        #pragma unroll
        for (int t = 0; t < 4; ++t) {
            const float tot = part[0][t][vloc] + part[1][t][vloc]
                            + part[2][t][vloc] + part[3][t][vloc];
            vg = (vg + tot) * 0.5f;
            const float g = (vg >= 0.5f) ? 1.f : 0.f;
            gate8[t][vloc] = (g != 0.f) ? 0x38 : 0x00;
            vg *= (1.f - g);
        }
    }
    __syncthreads();

    const uint8_t gb0 = gate8[0][vloc], gb1 = gate8[1][vloc];
    const uint8_t gb2 = gate8[2][vloc], gb3 = gate8[3][vloc];

    #pragma unroll
    for (int half = 0; half < 2; ++half) {
        uint32_t w0[4] = {0,0,0,0}, w1[4] = {0,0,0,0}, w2[4] = {0,0,0,0}, w3[4] = {0,0,0,0};
        #pragma unroll
        for (int j = 0; j < 16; ++j) {
            const int d = d0 + half * 16 + j;
            const int wi = j >> 2, sh = (j & 3) * 8;
            float vmk = 0.f, s;
            vmk = (vmk + __bfloat162float(k[IDX(0, d)])) * 0.5f;
            s = (vmk >= 1.f) ? 1.f : 0.f;
            if (s != 0.f) w0[wi] |= (uint32_t)gb0 << sh;
            vmk *= (1.f - s);
            vmk = (vmk + __bfloat162float(k[IDX(1, d)])) * 0.5f;
            s = (vmk >= 1.f) ? 1.f : 0.f;
            if (s != 0.f) w1[wi] |= (uint32_t)gb1 << sh;
            vmk *= (1.f - s);
            vmk = (vmk + __bfloat162float(k[IDX(2, d)])) * 0.5f;
            s = (vmk >= 1.f) ? 1.f : 0.f;
            if (s != 0.f) w2[wi] |= (uint32_t)gb2 << sh;
            vmk *= (1.f - s);
            vmk = (vmk + __bfloat162float(k[IDX(3, d)])) * 0.5f;
            s = (vmk >= 1.f) ? 1.f : 0.f;
            if (s != 0.f) w3[wi] |= (uint32_t)gb3 << sh;
        }
        const size_t base = (size_t)v * D_ + d0 + half * 16;
        *(uint4*)(sp8 + (size_t)(0 * B_ + b) * V_ * D_ + base) = make_uint4(w0[0], w0[1], w0[2], w0[3]);
        *(uint4*)(sp8 + (size_t)(1 * B_ + b) * V_ * D_ + base) = make_uint4(w1[0], w1[1], w1[2], w1[3]);
        *(uint4*)(sp8 + (size_t)(2 * B_ + b) * V_ * D_ + base) = make_uint4(w2[0], w2[1], w2[2], w2[3]);
        *(uint4*)(sp8 + (size_t)(3 * B_ + b) * V_ * D_ + base) = make_uint4(w3[0], w3[1], w3[2], w3[3]);
    }
#undef IDX
}

// ---------------------------------------------------------------------------
extern "C" void kernel_launch(void* const* d_in, const int* in_sizes, int n_in,
                              void* d_out, int out_size) {
    const float* x  = (const float*)d_in[0];
    const float* Wq = (const float*)d_in[1];
    const float* qg = (const float*)d_in[2];
    const float* qb = (const float*)d_in[3];
    const float* qm = (const float*)d_in[4];
    const float* qv = (const float*)d_in[5];
    const float* Wk = (const float*)d_in[6];
    const float* kg = (const float*)d_in[7];
    const float* kb = (const float*)d_in[8];
    const float* km = (const float*)d_in[9];
    const float* kv = (const float*)d_in[10];
    const float* Wp = (const float*)d_in[11];
    const float* pg = (const float*)d_in[12];
    const float* pb = (const float*)d_in[13];
    const float* pm = (const float*)d_in[14];
    const float* pv = (const float*)d_in[15];
    float* out = (float*)d_out;

    __nv_bfloat16 *xb, *qp, *kp, *wq, *wk;
    uint8_t *sp8, *wp8;
    cudaGetSymbolAddress((void**)&xb, g_xb);
    cudaGetSymbolAddress((void**)&qp, g_qpre);
    cudaGetSymbolAddress((void**)&kp, g_kpre);
    cudaGetSymbolAddress((void**)&sp8, g_sp8);
    cudaGetSymbolAddress((void**)&wq, g_wq);
    cudaGetSymbolAddress((void**)&wk, g_wk);
    cudaGetSymbolAddress((void**)&wp8, g_wp8);

    cudaFuncSetAttribute(gemm_qk_bf16, cudaFuncAttributeMaxDynamicSharedMemorySize, SMEM_BF16);
    cudaFuncSetAttribute(gemm_bn_fp8,  cudaFuncAttributeMaxDynamicSharedMemorySize, SMEM_FP8);

    convert_all_kernel<<<XBLOCKS + WBLOCKS, 256>>>(x, xb, Wq, Wk, Wp, wq, wk, wp8);

    gemm_qk_bf16<<<dim3(Z_, 8, 2), 256, SMEM_BF16>>>(
        wq, wk, xb, qg, qb, qm, qv, kg, kb, km, kv, qp, kp);
    lif_gate_kernel<<<dim3(B_, 4, 2), 512>>>(qp, kp, sp8);
    gemm_bn_fp8<<<dim3(Z_, D_ / 128, V_ / 128), 256, SMEM_FP8>>>(
        wp8, sp8, pg, pb, pm, pv, qp);
    lif_final_kernel<<<PLANE / 1024, 256>>>(qp, out);
}

// round 12
// speedup vs baseline: 1.0703x; 1.0651x over previous
#include <cuda_runtime.h>
#include <cuda_bf16.h>
#include <cuda_fp8.h>
#include <cstdint>

#define T_ 4
#define B_ 64
#define D_ 512
#define V_ 256
#define Z_ (T_*B_)            // 256
#define PLANE (B_*D_*V_)
#define TOTAL (Z_*D_*V_)      // 33554432

// ---------------- scratch ----------------
__device__ __nv_bfloat16 g_xb[TOTAL];     // x bf16, native [z][d][v]
__device__ __nv_bfloat16 g_qpre[TOTAL];   // [z][o][v]
__device__ __nv_bfloat16 g_kpre[TOTAL];   // [z][o][v]
__device__ uint8_t       g_sp8[TOTAL];    // gate*k spikes e4m3, [z][v][d]
__device__ __nv_bfloat16 g_wq[D_*D_];
__device__ __nv_bfloat16 g_wk[D_*D_];
__device__ uint8_t       g_wp8[D_*D_];    // Wp e4m3 [o][d]

// ---------------- helpers ----------------
__device__ __forceinline__ uint32_t smem_u32(const void* p) {
    uint32_t a;
    asm("{ .reg .u64 t; cvta.to.shared.u64 t, %1; cvt.u32.u64 %0, t; }" : "=r"(a) : "l"(p));
    return a;
}
__device__ __forceinline__ void cp16(uint32_t sdst, const void* gsrc) {
    asm volatile("cp.async.cg.shared.global [%0], [%1], 16;" :: "r"(sdst), "l"(gsrc) : "memory");
}
#define CP_COMMIT() asm volatile("cp.async.commit_group;" ::: "memory")
#define CP_WAIT1()  asm volatile("cp.async.wait_group 1;" ::: "memory")
#define CP_WAIT0()  asm volatile("cp.async.wait_group 0;" ::: "memory")

__device__ __forceinline__ void ldsm_x4(uint32_t* r, uint32_t addr) {
    asm volatile("ldmatrix.sync.aligned.m8n8.x4.shared.b16 {%0,%1,%2,%3}, [%4];"
        : "=r"(r[0]), "=r"(r[1]), "=r"(r[2]), "=r"(r[3]) : "r"(addr));
}
__device__ __forceinline__ void ldsm_x4_t(uint32_t* r, uint32_t addr) {
    asm volatile("ldmatrix.sync.aligned.m8n8.x4.trans.shared.b16 {%0,%1,%2,%3}, [%4];"
        : "=r"(r[0]), "=r"(r[1]), "=r"(r[2]), "=r"(r[3]) : "r"(addr));
}
__device__ __forceinline__ void mma_bf16(float* d, const uint32_t* a, uint32_t b0, uint32_t b1) {
    asm volatile("mma.sync.aligned.m16n8k16.row.col.f32.bf16.bf16.f32 "
        "{%0,%1,%2,%3}, {%4,%5,%6,%7}, {%8,%9}, {%0,%1,%2,%3};"
        : "+f"(d[0]), "+f"(d[1]), "+f"(d[2]), "+f"(d[3])
        : "r"(a[0]), "r"(a[1]), "r"(a[2]), "r"(a[3]), "r"(b0), "r"(b1));
}
__device__ __forceinline__ void mma_fp8(float* d, const uint32_t* a, uint32_t b0, uint32_t b1) {
    asm volatile("mma.sync.aligned.m16n8k32.row.col.f32.e4m3.e4m3.f32 "
        "{%0,%1,%2,%3}, {%4,%5,%6,%7}, {%8,%9}, {%0,%1,%2,%3};"
        : "+f"(d[0]), "+f"(d[1]), "+f"(d[2]), "+f"(d[3])
        : "r"(a[0]), "r"(a[1]), "r"(a[2]), "r"(a[3]), "r"(b0), "r"(b1));
}

// ---------------------------------------------------------------------------
// Stage-1/2 GEMM (bf16) + folded BN, ONE launch for Wq+Wk.
// NEW: K-chunk = 64 (8 chunks, half the barriers, 64 MMAs per sync).
// CTA 128(o) x 128(v), 8 warps = 4(o:32) x 2(v:64), 3-stage cp.async,
// 2 CTAs/SM (105KB SMEM each). A pitch 144B, B pitch 272B (both conflict-free).
// ---------------------------------------------------------------------------
#define A_STG 18432            // 128 rows * 144 B
#define B_STG 17408            // 64 rows * 272 B
#define SMEM_BF16 (3*(A_STG + B_STG))   // 107520

__global__ void __launch_bounds__(256, 2) gemm_qk_bf16(
    const __nv_bfloat16* __restrict__ Wq_, const __nv_bfloat16* __restrict__ Wk_,
    const __nv_bfloat16* __restrict__ X,
    const float* __restrict__ qg, const float* __restrict__ qb,
    const float* __restrict__ qm, const float* __restrict__ qv,
    const float* __restrict__ kg, const float* __restrict__ kb,
    const float* __restrict__ km, const float* __restrict__ kv,
    __nv_bfloat16* __restrict__ Q, __nv_bfloat16* __restrict__ K)
{
    extern __shared__ __align__(16) char smem[];
    __shared__ float sScale[128], sBias[128];

    const int tid = threadIdx.x, wid = tid >> 5, lane = tid & 31;
    const int z = blockIdx.x;
    const int which = blockIdx.y >> 2;          // 0 = q, 1 = k
    const int o0 = (blockIdx.y & 3) * 128;
    const int v0 = blockIdx.z * 128;

    const __nv_bfloat16* W = which ? Wk_ : Wq_;
    const float* gamma = which ? kg : qg;
    const float* beta  = which ? kb : qb;
    const float* mean  = which ? km : qm;
    const float* var   = which ? kv : qv;
    __nv_bfloat16* O   = which ? K : Q;

    const __nv_bfloat16* Wb = W + (size_t)o0 * D_;
    const __nv_bfloat16* Xb = X + (size_t)z * D_ * V_ + v0;

    if (tid < 128) {
        const float inv = gamma[o0 + tid] * rsqrtf(var[o0 + tid] + 1e-5f);
        sScale[tid] = inv;
        sBias[tid]  = beta[o0 + tid] - mean[o0 + tid] * inv;
    }

    const uint32_t sA = smem_u32(smem);
    const uint32_t sB = sA + 3 * A_STG;
    const int wm = wid & 3, wv = wid >> 2;

    float acc[2][8][4];
    #pragma unroll
    for (int i = 0; i < 2; ++i)
        #pragma unroll
        for (int j = 0; j < 8; ++j)
            #pragma unroll
            for (int q = 0; q < 4; ++q) acc[i][j][q] = 0.f;

    auto issue = [&](int s, int kc) {
        const uint32_t ab = sA + s * A_STG;
        const uint32_t bb = sB + s * B_STG;
        #pragma unroll
        for (int i = 0; i < 4; ++i) {       // A: 128 rows x 8 x 16B
            const int idx = tid + i * 256;
            const int row = idx >> 3, c = idx & 7;
            cp16(ab + row * 144 + c * 16, Wb + (size_t)row * D_ + kc + c * 8);
        }
        #pragma unroll
        for (int i = 0; i < 4; ++i) {       // B: 64 rows x 16 x 16B
            const int idx = tid + i * 256;
            const int row = idx >> 4, c = idx & 15;
            cp16(bb + row * 272 + c * 16, Xb + (size_t)(kc + row) * V_ + c * 8);
        }
        CP_COMMIT();
    };

    issue(0, 0);
    issue(1, 64);

    #pragma unroll 1
    for (int c = 0; c < 8; ++c) {
        if (c < 7) CP_WAIT1(); else CP_WAIT0();
        __syncthreads();
        if (c < 6) issue((c + 2) % 3, (c + 2) * 64);

        const int s = c % 3;
        const uint32_t aB = sA + s * A_STG;
        const uint32_t bB = sB + s * B_STG;

        #pragma unroll
        for (int kk = 0; kk < 4; ++kk) {
            uint32_t af[2][4];
            #pragma unroll
            for (int mt = 0; mt < 2; ++mt) {
                const int row = wm * 32 + mt * 16 + (lane & 15);
                ldsm_x4(af[mt], aB + row * 144 + kk * 32 + (lane >> 4) * 16);
            }
            uint32_t bfr[4][4];
            const int sub = lane >> 3;
            const int krow = kk * 16 + (sub & 1) * 8 + (lane & 7);
            #pragma unroll
            for (int g = 0; g < 4; ++g) {
                const int ncol = wv * 64 + g * 16 + (sub >> 1) * 8;
                ldsm_x4_t(bfr[g], bB + krow * 272 + ncol * 2);
            }
            #pragma unroll
            for (int mt = 0; mt < 2; ++mt)
                #pragma unroll
                for (int g = 0; g < 4; ++g) {
                    mma_bf16(acc[mt][g * 2 + 0], af[mt], bfr[g][0], bfr[g][1]);
                    mma_bf16(acc[mt][g * 2 + 1], af[mt], bfr[g][2], bfr[g][3]);
                }
        }
    }

    #pragma unroll
    for (int mt = 0; mt < 2; ++mt) {
        const int oL = wm * 32 + mt * 16 + (lane >> 2);
        #pragma unroll
        for (int h = 0; h < 2; ++h) {
            const int o = oL + h * 8;
            const float sc = sScale[o], bi = sBias[o];
            __nv_bfloat16* orow = O + ((size_t)z * D_ + o0 + o) * V_ + v0;
            #pragma unroll
            for (int nt = 0; nt < 8; ++nt) {
                const int v = wv * 64 + nt * 8 + (lane & 3) * 2;
                const float fa = acc[mt][nt][2 * h]     * sc + bi;
                const float fb = acc[mt][nt][2 * h + 1] * sc + bi;
                const __nv_bfloat162 h2 = __floats2bfloat162_rn(fa, fb);
                *(uint32_t*)(orow + v) = *(const uint32_t*)&h2;
            }
        }
    }
}

// ---------------------------------------------------------------------------
// Fused stage-3: fp8 GEMM + BN + final LIF -> d_out fp32 (R9 version verbatim
// — measured 133us, beats unfused 116 + lif_final + gap).
// ---------------------------------------------------------------------------
#define FA_CHUNK 10240
#define FA_TOTAL (8*FA_CHUNK)
#define FB_STG 5120
#define SMEM_F (FA_TOTAL + 3*FB_STG)

__global__ void __launch_bounds__(256, 2) gemm_fp8_lif(
    const uint8_t* __restrict__ W8,
    const uint8_t* __restrict__ S8,
    const float* __restrict__ gamma, const float* __restrict__ beta,
    const float* __restrict__ mean, const float* __restrict__ var,
    float* __restrict__ out)
{
    extern __shared__ __align__(16) char smem[];
    __shared__ float sScale[128], sBias[128];

    const int tid = threadIdx.x, wid = tid >> 5, lane = tid & 31;
    const int b = blockIdx.x, o0 = blockIdx.y * 128, v0 = blockIdx.z * 64;

    const uint8_t* Ab = W8 + (size_t)o0 * D_;

    if (tid < 128) {
        const float inv = gamma[o0 + tid] * rsqrtf(var[o0 + tid] + 1e-5f);
        sScale[tid] = inv;
        sBias[tid]  = beta[o0 + tid] - mean[o0 + tid] * inv;
    }

    const uint32_t sA = smem_u32(smem);
    const uint32_t sB = sA + FA_TOTAL;
    const int wm = wid & 3, wv = wid >> 2;

    #pragma unroll
    for (int i = 0; i < 16; ++i) {
        const int idx = tid + i * 256;
        const int kc = idx >> 9;
        const int rem = idx & 511;
        const int row = rem >> 2, cc = rem & 3;
        cp16(sA + kc * FA_CHUNK + row * 80 + cc * 16,
             Ab + (size_t)row * D_ + kc * 64 + cc * 16);
    }
    CP_COMMIT();

    auto issueB = [&](int s, int j) {
        const int t = j >> 3, kc = (j & 7) * 64;
        const uint8_t* Bb = S8 + ((size_t)(t * B_ + b) * V_ + v0) * D_;
        const int row = tid >> 2, cc = tid & 3;
        cp16(sB + s * FB_STG + row * 80 + cc * 16,
             Bb + (size_t)row * D_ + kc + cc * 16);
        CP_COMMIT();
    };

    issueB(0, 0);
    issueB(1, 1);
    CP_WAIT0();
    __syncthreads();

    float vm[2][2][4][2];
    #pragma unroll
    for (int i = 0; i < 2; ++i)
        #pragma unroll
        for (int j = 0; j < 2; ++j)
            #pragma unroll
            for (int q = 0; q < 4; ++q) { vm[i][j][q][0] = 0.f; vm[i][j][q][1] = 0.f; }

    float acc[2][4][4];
    #pragma unroll
    for (int i = 0; i < 2; ++i)
        #pragma unroll
        for (int j = 0; j < 4; ++j)
            #pragma unroll
            for (int q = 0; q < 4; ++q) acc[i][j][q] = 0.f;

    #pragma unroll 1
    for (int j = 0; j < 32; ++j) {
        if (j > 0) {
            if (j < 31) CP_WAIT1(); else CP_WAIT0();
        }
        __syncthreads();
        if (j < 30) issueB((j + 2) % 3, j + 2);

        const uint32_t aB = sA + (j & 7) * FA_CHUNK;
        const uint32_t bB = sB + (j % 3) * FB_STG;

        #pragma unroll
        for (int kk = 0; kk < 2; ++kk) {
            uint32_t af[2][4];
            #pragma unroll
            for (int mt = 0; mt < 2; ++mt) {
                const int row = wm * 32 + mt * 16 + (lane & 15);
                ldsm_x4(af[mt], aB + row * 80 + kk * 32 + (lane >> 4) * 16);
            }
            uint32_t bfr[2][4];
            #pragma unroll
            for (int g = 0; g < 2; ++g) {
                const int row = wv * 32 + g * 16 + (lane & 15);
                ldsm_x4(bfr[g], bB + row * 80 + kk * 32 + (lane >> 4) * 16);
            }
            #pragma unroll
            for (int mt = 0; mt < 2; ++mt)
                #pragma unroll
                for (int g = 0; g < 2; ++g) {
                    mma_fp8(acc[mt][g * 2 + 0], af[mt], bfr[g][0], bfr[g][2]);
                    mma_fp8(acc[mt][g * 2 + 1], af[mt], bfr[g][1], bfr[g][3]);
                }
        }

        if ((j & 7) == 7) {
            const int t = j >> 3;
            const size_t zofs = (size_t)(t * B_ + b) * D_;
            #pragma unroll
            for (int mt = 0; mt < 2; ++mt) {
                const int oL = wm * 32 + mt * 16 + (lane >> 2);
                #pragma unroll
                for (int h = 0; h < 2; ++h) {
                    const int o = oL + h * 8;
                    const float sc = sScale[o], bi = sBias[o];
                    float* orow = out + (zofs + o0 + o) * V_ + v0;
                    #pragma unroll
                    for (int nt = 0; nt < 4; ++nt) {
                        const int v = wv * 32 + nt * 8 + (lane & 3) * 2;
                        const float f0 = acc[mt][nt][2 * h]     * sc + bi;
                        const float f1 = acc[mt][nt][2 * h + 1] * sc + bi;
                        float m0 = (vm[mt][h][nt][0] + f0) * 0.5f;
                        float m1 = (vm[mt][h][nt][1] + f1) * 0.5f;
                        const float s0 = (m0 >= 1.f) ? 1.f : 0.f;
                        const float s1 = (m1 >= 1.f) ? 1.f : 0.f;
                        vm[mt][h][nt][0] = m0 * (1.f - s0);
                        vm[mt][h][nt][1] = m1 * (1.f - s1);
                        *(float2*)(orow + v) = make_float2(s0, s1);
                        acc[mt][nt][2 * h] = 0.f;
                        acc[mt][nt][2 * h + 1] = 0.f;
                    }
                }
            }
        }
    }
}

// ---------------------------------------------------------------------------
// Single converter launch (unchanged).
// ---------------------------------------------------------------------------
#define XBLOCKS (TOTAL / 1024)
#define WBLOCKS (D_ * D_ / 256)

__global__ void convert_all_kernel(
    const float* __restrict__ x, __nv_bfloat16* __restrict__ xb,
    const float* __restrict__ wq, const float* __restrict__ wk,
    const float* __restrict__ wp,
    __nv_bfloat16* __restrict__ dq, __nv_bfloat16* __restrict__ dk,
    uint8_t* __restrict__ dp)
{
    if (blockIdx.x < XBLOCKS) {
        const size_t i = (size_t)blockIdx.x * 256 + threadIdx.x;
        const float4 f = ((const float4*)x)[i];
        const __nv_bfloat162 a = __floats2bfloat162_rn(f.x, f.y);
        const __nv_bfloat162 b = __floats2bfloat162_rn(f.z, f.w);
        uint2 u;
        u.x = *(const uint32_t*)&a;
        u.y = *(const uint32_t*)&b;
        ((uint2*)xb)[i] = u;
    } else {
        const int i = (blockIdx.x - XBLOCKS) * 256 + threadIdx.x;
        dq[i] = __float2bfloat16(wq[i]);
        dk[i] = __float2bfloat16(wk[i]);
        dp[i] = (uint8_t)__nv_cvt_float_to_fp8(wp[i], __NV_SATFINITE, __NV_E4M3);
    }
}

// ---------------------------------------------------------------------------
// lif_gate (unchanged from R9).
// ---------------------------------------------------------------------------
__global__ void __launch_bounds__(512, 2) lif_gate_kernel(
    const __nv_bfloat16* __restrict__ q,
    const __nv_bfloat16* __restrict__ k,
    uint8_t* __restrict__ sp8)
{
    __shared__ float part[4][4][128];
    __shared__ uint8_t gate8[4][128];

    const int b = blockIdx.x, h = blockIdx.y;
    const int tid = threadIdx.x;
    const int c = tid >> 7, vloc = tid & 127;
    const int v = blockIdx.z * 128 + vloc;
    const int d0 = h * 128 + c * 32;

#define IDX(t, d) ((((size_t)((t) * B_ + b)) * D_ + (d)) * V_ + v)
    float qs0 = 0.f, qs1 = 0.f, qs2 = 0.f, qs3 = 0.f;
    #pragma unroll 4
    for (int j = 0; j < 32; ++j) {
        const int d = d0 + j;
        float vmq = 0.f, s;
        vmq = (vmq + __bfloat162float(q[IDX(0, d)])) * 0.5f;
        s = (vmq >= 1.f) ? 1.f : 0.f; qs0 += s; vmq *= (1.f - s);
        vmq = (vmq + __bfloat162float(q[IDX(1, d)])) * 0.5f;
        s = (vmq >= 1.f) ? 1.f : 0.f; qs1 += s; vmq *= (1.f - s);
        vmq = (vmq + __bfloat162float(q[IDX(2, d)])) * 0.5f;
        s = (vmq >= 1.f) ? 1.f : 0.f; qs2 += s; vmq *= (1.f - s);
        vmq = (vmq + __bfloat162float(q[IDX(3, d)])) * 0.5f;
        s = (vmq >= 1.f) ? 1.f : 0.f; qs3 += s;
    }
    part[c][0][vloc] = qs0; part[c][1][vloc] = qs1;
    part[c][2][vloc] = qs2; part[c][3][vloc] = qs3;
    __syncthreads();

    if (c == 0) {
        float vg = 0.f;
        #pragma unroll
        for (int t = 0; t < 4; ++t) {
            const float tot = part[0][t][vloc] + part[1][t][vloc]
                            + part[2][t][vloc] + part[3][t][vloc];
            vg = (vg + tot) * 0.5f;
            const float g = (vg >= 0.5f) ? 1.f : 0.f;
            gate8[t][vloc] = (g != 0.f) ? 0x38 : 0x00;
            vg *= (1.f - g);
        }
    }
    __syncthreads();

    const uint8_t gb0 = gate8[0][vloc], gb1 = gate8[1][vloc];
    const uint8_t gb2 = gate8[2][vloc], gb3 = gate8[3][vloc];

    #pragma unroll
    for (int half = 0; half < 2; ++half) {
        uint32_t w0[4] = {0,0,0,0}, w1[4] = {0,0,0,0}, w2[4] = {0,0,0,0}, w3[4] = {0,0,0,0};
        #pragma unroll
        for (int j = 0; j < 16; ++j) {
            const int d = d0 + half * 16 + j;
            const int wi = j >> 2, sh = (j & 3) * 8;
            float vmk = 0.f, s;
            vmk = (vmk + __bfloat162float(k[IDX(0, d)])) * 0.5f;
            s = (vmk >= 1.f) ? 1.f : 0.f;
            if (s != 0.f) w0[wi] |= (uint32_t)gb0 << sh;
            vmk *= (1.f - s);
            vmk = (vmk + __bfloat162float(k[IDX(1, d)])) * 0.5f;
            s = (vmk >= 1.f) ? 1.f : 0.f;
            if (s != 0.f) w1[wi] |= (uint32_t)gb1 << sh;
            vmk *= (1.f - s);
            vmk = (vmk + __bfloat162float(k[IDX(2, d)])) * 0.5f;
            s = (vmk >= 1.f) ? 1.f : 0.f;
            if (s != 0.f) w2[wi] |= (uint32_t)gb2 << sh;
            vmk *= (1.f - s);
            vmk = (vmk + __bfloat162float(k[IDX(3, d)])) * 0.5f;
            s = (vmk >= 1.f) ? 1.f : 0.f;
            if (s != 0.f) w3[wi] |= (uint32_t)gb3 << sh;
        }
        const size_t base = (size_t)v * D_ + d0 + half * 16;
        *(uint4*)(sp8 + (size_t)(0 * B_ + b) * V_ * D_ + base) = make_uint4(w0[0], w0[1], w0[2], w0[3]);
        *(uint4*)(sp8 + (size_t)(1 * B_ + b) * V_ * D_ + base) = make_uint4(w1[0], w1[1], w1[2], w1[3]);
        *(uint4*)(sp8 + (size_t)(2 * B_ + b) * V_ * D_ + base) = make_uint4(w2[0], w2[1], w2[2], w2[3]);
        *(uint4*)(sp8 + (size_t)(3 * B_ + b) * V_ * D_ + base) = make_uint4(w3[0], w3[1], w3[2], w3[3]);
    }
#undef IDX
}

// ---------------------------------------------------------------------------
extern "C" void kernel_launch(void* const* d_in, const int* in_sizes, int n_in,
                              void* d_out, int out_size) {
    const float* x  = (const float*)d_in[0];
    const float* Wq = (const float*)d_in[1];
    const float* qg = (const float*)d_in[2];
    const float* qb = (const float*)d_in[3];
    const float* qm = (const float*)d_in[4];
    const float* qv = (const float*)d_in[5];
    const float* Wk = (const float*)d_in[6];
    const float* kg = (const float*)d_in[7];
    const float* kb = (const float*)d_in[8];
    const float* km = (const float*)d_in[9];
    const float* kv = (const float*)d_in[10];
    const float* Wp = (const float*)d_in[11];
    const float* pg = (const float*)d_in[12];
    const float* pb = (const float*)d_in[13];
    const float* pm = (const float*)d_in[14];
    const float* pv = (const float*)d_in[15];
    float* out = (float*)d_out;

    __nv_bfloat16 *xb, *qp, *kp, *wq, *wk;
    uint8_t *sp8, *wp8;
    cudaGetSymbolAddress((void**)&xb, g_xb);
    cudaGetSymbolAddress((void**)&qp, g_qpre);
    cudaGetSymbolAddress((void**)&kp, g_kpre);
    cudaGetSymbolAddress((void**)&sp8, g_sp8);
    cudaGetSymbolAddress((void**)&wq, g_wq);
    cudaGetSymbolAddress((void**)&wk, g_wk);
    cudaGetSymbolAddress((void**)&wp8, g_wp8);

    cudaFuncSetAttribute(gemm_qk_bf16, cudaFuncAttributeMaxDynamicSharedMemorySize, SMEM_BF16);
    cudaFuncSetAttribute(gemm_fp8_lif, cudaFuncAttributeMaxDynamicSharedMemorySize, SMEM_F);

    convert_all_kernel<<<XBLOCKS + WBLOCKS, 256>>>(x, xb, Wq, Wk, Wp, wq, wk, wp8);

    gemm_qk_bf16<<<dim3(Z_, 8, 2), 256, SMEM_BF16>>>(
        wq, wk, xb, qg, qb, qm, qv, kg, kb, km, kv, qp, kp);
    lif_gate_kernel<<<dim3(B_, 4, 2), 512>>>(qp, kp, sp8);
    gemm_fp8_lif<<<dim3(B_, D_ / 128, V_ / 64), 256, SMEM_F>>>(
        wp8, sp8, pg, pb, pm, pv, out);
}

// round 13
// speedup vs baseline: 1.0957x; 1.0237x over previous
#include <cuda_runtime.h>
#include <cuda_bf16.h>
#include <cuda_fp8.h>
#include <cstdint>

#define T_ 4
#define B_ 64
#define D_ 512
#define V_ 256
#define Z_ (T_*B_)            // 256
#define PLANE (B_*D_*V_)
#define TOTAL (Z_*D_*V_)      // 33554432

// ---------------- scratch ----------------
__device__ __nv_bfloat16 g_xb[TOTAL];     // x bf16, native [z][d][v]
__device__ __nv_bfloat16 g_qpre[TOTAL];   // [z][o][v]
__device__ __nv_bfloat16 g_kpre[TOTAL];   // [z][o][v]
__device__ uint8_t       g_sp8[TOTAL];    // gate*k spikes e4m3, [z][v][d]
__device__ __nv_bfloat16 g_wq[D_*D_];
__device__ __nv_bfloat16 g_wk[D_*D_];
__device__ uint8_t       g_wp8[D_*D_];    // Wp e4m3 [o][d]

// ---------------- helpers ----------------
__device__ __forceinline__ uint32_t smem_u32(const void* p) {
    uint32_t a;
    asm("{ .reg .u64 t; cvta.to.shared.u64 t, %1; cvt.u32.u64 %0, t; }" : "=r"(a) : "l"(p));
    return a;
}
__device__ __forceinline__ void cp16(uint32_t sdst, const void* gsrc) {
    asm volatile("cp.async.cg.shared.global [%0], [%1], 16;" :: "r"(sdst), "l"(gsrc) : "memory");
}
#define CP_COMMIT() asm volatile("cp.async.commit_group;" ::: "memory")
#define CP_WAIT1()  asm volatile("cp.async.wait_group 1;" ::: "memory")
#define CP_WAIT0()  asm volatile("cp.async.wait_group 0;" ::: "memory")

__device__ __forceinline__ void ldsm_x4(uint32_t* r, uint32_t addr) {
    asm volatile("ldmatrix.sync.aligned.m8n8.x4.shared.b16 {%0,%1,%2,%3}, [%4];"
        : "=r"(r[0]), "=r"(r[1]), "=r"(r[2]), "=r"(r[3]) : "r"(addr));
}
__device__ __forceinline__ void ldsm_x4_t(uint32_t* r, uint32_t addr) {
    asm volatile("ldmatrix.sync.aligned.m8n8.x4.trans.shared.b16 {%0,%1,%2,%3}, [%4];"
        : "=r"(r[0]), "=r"(r[1]), "=r"(r[2]), "=r"(r[3]) : "r"(addr));
}
__device__ __forceinline__ void mma_bf16(float* d, const uint32_t* a, uint32_t b0, uint32_t b1) {
    asm volatile("mma.sync.aligned.m16n8k16.row.col.f32.bf16.bf16.f32 "
        "{%0,%1,%2,%3}, {%4,%5,%6,%7}, {%8,%9}, {%0,%1,%2,%3};"
        : "+f"(d[0]), "+f"(d[1]), "+f"(d[2]), "+f"(d[3])
        : "r"(a[0]), "r"(a[1]), "r"(a[2]), "r"(a[3]), "r"(b0), "r"(b1));
}
__device__ __forceinline__ void mma_fp8(float* d, const uint32_t* a, uint32_t b0, uint32_t b1) {
    asm volatile("mma.sync.aligned.m16n8k32.row.col.f32.e4m3.e4m3.f32 "
        "{%0,%1,%2,%3}, {%4,%5,%6,%7}, {%8,%9}, {%0,%1,%2,%3};"
        : "+f"(d[0]), "+f"(d[1]), "+f"(d[2]), "+f"(d[3])
        : "r"(a[0]), "r"(a[1]), "r"(a[2]), "r"(a[3]), "r"(b0), "r"(b1));
}

// ---------------------------------------------------------------------------
// Stage-1/2 GEMM (bf16) + folded BN, ONE launch for Wq+Wk.
// K-chunk = 64 (8 chunks, 64 MMAs per sync) — R12 version, proven win.
// ---------------------------------------------------------------------------
#define A_STG 18432            // 128 rows * 144 B
#define B_STG 17408            // 64 rows * 272 B
#define SMEM_BF16 (3*(A_STG + B_STG))   // 107520

__global__ void __launch_bounds__(256, 2) gemm_qk_bf16(
    const __nv_bfloat16* __restrict__ Wq_, const __nv_bfloat16* __restrict__ Wk_,
    const __nv_bfloat16* __restrict__ X,
    const float* __restrict__ qg, const float* __restrict__ qb,
    const float* __restrict__ qm, const float* __restrict__ qv,
    const float* __restrict__ kg, const float* __restrict__ kb,
    const float* __restrict__ km, const float* __restrict__ kv,
    __nv_bfloat16* __restrict__ Q, __nv_bfloat16* __restrict__ K)
{
    extern __shared__ __align__(16) char smem[];
    __shared__ float sScale[128], sBias[128];

    const int tid = threadIdx.x, wid = tid >> 5, lane = tid & 31;
    const int z = blockIdx.x;
    const int which = blockIdx.y >> 2;          // 0 = q, 1 = k
    const int o0 = (blockIdx.y & 3) * 128;
    const int v0 = blockIdx.z * 128;

    const __nv_bfloat16* W = which ? Wk_ : Wq_;
    const float* gamma = which ? kg : qg;
    const float* beta  = which ? kb : qb;
    const float* mean  = which ? km : qm;
    const float* var   = which ? kv : qv;
    __nv_bfloat16* O   = which ? K : Q;

    const __nv_bfloat16* Wb = W + (size_t)o0 * D_;
    const __nv_bfloat16* Xb = X + (size_t)z * D_ * V_ + v0;

    if (tid < 128) {
        const float inv = gamma[o0 + tid] * rsqrtf(var[o0 + tid] + 1e-5f);
        sScale[tid] = inv;
        sBias[tid]  = beta[o0 + tid] - mean[o0 + tid] * inv;
    }

    const uint32_t sA = smem_u32(smem);
    const uint32_t sB = sA + 3 * A_STG;
    const int wm = wid & 3, wv = wid >> 2;

    float acc[2][8][4];
    #pragma unroll
    for (int i = 0; i < 2; ++i)
        #pragma unroll
        for (int j = 0; j < 8; ++j)
            #pragma unroll
            for (int q = 0; q < 4; ++q) acc[i][j][q] = 0.f;

    auto issue = [&](int s, int kc) {
        const uint32_t ab = sA + s * A_STG;
        const uint32_t bb = sB + s * B_STG;
        #pragma unroll
        for (int i = 0; i < 4; ++i) {       // A: 128 rows x 8 x 16B
            const int idx = tid + i * 256;
            const int row = idx >> 3, c = idx & 7;
            cp16(ab + row * 144 + c * 16, Wb + (size_t)row * D_ + kc + c * 8);
        }
        #pragma unroll
        for (int i = 0; i < 4; ++i) {       // B: 64 rows x 16 x 16B
            const int idx = tid + i * 256;
            const int row = idx >> 4, c = idx & 15;
            cp16(bb + row * 272 + c * 16, Xb + (size_t)(kc + row) * V_ + c * 8);
        }
        CP_COMMIT();
    };

    issue(0, 0);
    issue(1, 64);

    #pragma unroll 1
    for (int c = 0; c < 8; ++c) {
        if (c < 7) CP_WAIT1(); else CP_WAIT0();
        __syncthreads();
        if (c < 6) issue((c + 2) % 3, (c + 2) * 64);

        const int s = c % 3;
        const uint32_t aB = sA + s * A_STG;
        const uint32_t bB = sB + s * B_STG;

        #pragma unroll
        for (int kk = 0; kk < 4; ++kk) {
            uint32_t af[2][4];
            #pragma unroll
            for (int mt = 0; mt < 2; ++mt) {
                const int row = wm * 32 + mt * 16 + (lane & 15);
                ldsm_x4(af[mt], aB + row * 144 + kk * 32 + (lane >> 4) * 16);
            }
            uint32_t bfr[4][4];
            const int sub = lane >> 3;
            const int krow = kk * 16 + (sub & 1) * 8 + (lane & 7);
            #pragma unroll
            for (int g = 0; g < 4; ++g) {
                const int ncol = wv * 64 + g * 16 + (sub >> 1) * 8;
                ldsm_x4_t(bfr[g], bB + krow * 272 + ncol * 2);
            }
            #pragma unroll
            for (int mt = 0; mt < 2; ++mt)
                #pragma unroll
                for (int g = 0; g < 4; ++g) {
                    mma_bf16(acc[mt][g * 2 + 0], af[mt], bfr[g][0], bfr[g][1]);
                    mma_bf16(acc[mt][g * 2 + 1], af[mt], bfr[g][2], bfr[g][3]);
                }
        }
    }

    #pragma unroll
    for (int mt = 0; mt < 2; ++mt) {
        const int oL = wm * 32 + mt * 16 + (lane >> 2);
        #pragma unroll
        for (int h = 0; h < 2; ++h) {
            const int o = oL + h * 8;
            const float sc = sScale[o], bi = sBias[o];
            __nv_bfloat16* orow = O + ((size_t)z * D_ + o0 + o) * V_ + v0;
            #pragma unroll
            for (int nt = 0; nt < 8; ++nt) {
                const int v = wv * 64 + nt * 8 + (lane & 3) * 2;
                const float fa = acc[mt][nt][2 * h]     * sc + bi;
                const float fb = acc[mt][nt][2 * h + 1] * sc + bi;
                const __nv_bfloat162 h2 = __floats2bfloat162_rn(fa, fb);
                *(uint32_t*)(orow + v) = *(const uint32_t*)&h2;
            }
        }
    }
}

// ---------------------------------------------------------------------------
// Fused stage-3: fp8 GEMM + BN + final LIF -> d_out fp32.
// NEW: B chunk widened to 128 fp8 k-elements (16 chunks total, half the
// barriers, 32 MMAs + 16 ldsm per barrier). A resident (80KB, loaded once).
// B stage: 64 rows x 144B pitch (conflict-free), 3 stages. 2 CTAs/SM.
// ---------------------------------------------------------------------------
#define FA_CHUNK 10240                   // per-64k A block: 128 rows * 80 B
#define FA_TOTAL (8*FA_CHUNK)            // 81920
#define FB_STG 9216                      // 64 rows * 144 B
#define SMEM_F (FA_TOTAL + 3*FB_STG)     // 109568

__global__ void __launch_bounds__(256, 2) gemm_fp8_lif(
    const uint8_t* __restrict__ W8,
    const uint8_t* __restrict__ S8,
    const float* __restrict__ gamma, const float* __restrict__ beta,
    const float* __restrict__ mean, const float* __restrict__ var,
    float* __restrict__ out)
{
    extern __shared__ __align__(16) char smem[];
    __shared__ float sScale[128], sBias[128];

    const int tid = threadIdx.x, wid = tid >> 5, lane = tid & 31;
    const int b = blockIdx.x, o0 = blockIdx.y * 128, v0 = blockIdx.z * 64;

    const uint8_t* Ab = W8 + (size_t)o0 * D_;

    if (tid < 128) {
        const float inv = gamma[o0 + tid] * rsqrtf(var[o0 + tid] + 1e-5f);
        sScale[tid] = inv;
        sBias[tid]  = beta[o0 + tid] - mean[o0 + tid] * inv;
    }

    const uint32_t sA = smem_u32(smem);
    const uint32_t sB = sA + FA_TOTAL;
    const int wm = wid & 3, wv = wid >> 2;

    // Preload entire A (Wp tile) once: 8 blocks x 128 rows x 64 B (pitch 80).
    #pragma unroll
    for (int i = 0; i < 16; ++i) {
        const int idx = tid + i * 256;        // 0..4095
        const int kc = idx >> 9;
        const int rem = idx & 511;
        const int row = rem >> 2, cc = rem & 3;
        cp16(sA + kc * FA_CHUNK + row * 80 + cc * 16,
             Ab + (size_t)row * D_ + kc * 64 + cc * 16);
    }
    CP_COMMIT();

    // B chunk j (0..15): t = j>>2, kc = (j&3)*128. 64 rows x 8 x 16B.
    auto issueB = [&](int s, int j) {
        const int t = j >> 2, kc = (j & 3) * 128;
        const uint8_t* Bb = S8 + ((size_t)(t * B_ + b) * V_ + v0) * D_;
        #pragma unroll
        for (int i = 0; i < 2; ++i) {
            const int idx = tid + i * 256;    // 0..511
            const int row = idx >> 3, cc = idx & 7;
            cp16(sB + s * FB_STG + row * 144 + cc * 16,
                 Bb + (size_t)row * D_ + kc + cc * 16);
        }
        CP_COMMIT();
    };

    issueB(0, 0);
    issueB(1, 1);
    CP_WAIT0();     // A + first two B chunks resident
    __syncthreads();

    float vm[2][2][4][2];   // membranes, persist across t
    #pragma unroll
    for (int i = 0; i < 2; ++i)
        #pragma unroll
        for (int j = 0; j < 2; ++j)
            #pragma unroll
            for (int q = 0; q < 4; ++q) { vm[i][j][q][0] = 0.f; vm[i][j][q][1] = 0.f; }

    float acc[2][4][4];
    #pragma unroll
    for (int i = 0; i < 2; ++i)
        #pragma unroll
        for (int j = 0; j < 4; ++j)
            #pragma unroll
            for (int q = 0; q < 4; ++q) acc[i][j][q] = 0.f;

    #pragma unroll 1
    for (int j = 0; j < 16; ++j) {
        if (j > 0) {
            if (j < 15) CP_WAIT1(); else CP_WAIT0();
        }
        __syncthreads();
        if (j < 14) issueB((j + 2) % 3, j + 2);

        const uint32_t bB = sB + (j % 3) * FB_STG;
        const int ablk = (j & 3) * 2;         // first of two 64-k A blocks

        #pragma unroll
        for (int kk = 0; kk < 4; ++kk) {
            const uint32_t aB = sA + (ablk + (kk >> 1)) * FA_CHUNK + (kk & 1) * 32;
            uint32_t af[2][4];
            #pragma unroll
            for (int mt = 0; mt < 2; ++mt) {
                const int row = wm * 32 + mt * 16 + (lane & 15);
                ldsm_x4(af[mt], aB + row * 80 + (lane >> 4) * 16);
            }
            uint32_t bfr[2][4];
            #pragma unroll
            for (int g = 0; g < 2; ++g) {
                const int row = wv * 32 + g * 16 + (lane & 15);
                ldsm_x4(bfr[g], bB + row * 144 + kk * 32 + (lane >> 4) * 16);
            }
            #pragma unroll
            for (int mt = 0; mt < 2; ++mt)
                #pragma unroll
                for (int g = 0; g < 2; ++g) {
                    mma_fp8(acc[mt][g * 2 + 0], af[mt], bfr[g][0], bfr[g][2]);
                    mma_fp8(acc[mt][g * 2 + 1], af[mt], bfr[g][1], bfr[g][3]);
                }
        }

        if ((j & 3) == 3) {
            // end of timestep t: BN + LIF + store, reset acc
            const int t = j >> 2;
            const size_t zofs = (size_t)(t * B_ + b) * D_;
            #pragma unroll
            for (int mt = 0; mt < 2; ++mt) {
                const int oL = wm * 32 + mt * 16 + (lane >> 2);
                #pragma unroll
                for (int h = 0; h < 2; ++h) {
                    const int o = oL + h * 8;
                    const float sc = sScale[o], bi = sBias[o];
                    float* orow = out + (zofs + o0 + o) * V_ + v0;
                    #pragma unroll
                    for (int nt = 0; nt < 4; ++nt) {
                        const int v = wv * 32 + nt * 8 + (lane & 3) * 2;
                        const float f0 = acc[mt][nt][2 * h]     * sc + bi;
                        const float f1 = acc[mt][nt][2 * h + 1] * sc + bi;
                        float m0 = (vm[mt][h][nt][0] + f0) * 0.5f;
                        float m1 = (vm[mt][h][nt][1] + f1) * 0.5f;
                        const float s0 = (m0 >= 1.f) ? 1.f : 0.f;
                        const float s1 = (m1 >= 1.f) ? 1.f : 0.f;
                        vm[mt][h][nt][0] = m0 * (1.f - s0);
                        vm[mt][h][nt][1] = m1 * (1.f - s1);
                        *(float2*)(orow + v) = make_float2(s0, s1);
                        acc[mt][nt][2 * h] = 0.f;
                        acc[mt][nt][2 * h + 1] = 0.f;
                    }
                }
            }
        }
    }
}

// ---------------------------------------------------------------------------
// Single converter launch (unchanged).
// ---------------------------------------------------------------------------
#define XBLOCKS (TOTAL / 1024)
#define WBLOCKS (D_ * D_ / 256)

__global__ void convert_all_kernel(
    const float* __restrict__ x, __nv_bfloat16* __restrict__ xb,
    const float* __restrict__ wq, const float* __restrict__ wk,
    const float* __restrict__ wp,
    __nv_bfloat16* __restrict__ dq, __nv_bfloat16* __restrict__ dk,
    uint8_t* __restrict__ dp)
{
    if (blockIdx.x < XBLOCKS) {
        const size_t i = (size_t)blockIdx.x * 256 + threadIdx.x;
        const float4 f = ((const float4*)x)[i];
        const __nv_bfloat162 a = __floats2bfloat162_rn(f.x, f.y);
        const __nv_bfloat162 b = __floats2bfloat162_rn(f.z, f.w);
        uint2 u;
        u.x = *(const uint32_t*)&a;
        u.y = *(const uint32_t*)&b;
        ((uint2*)xb)[i] = u;
    } else {
        const int i = (blockIdx.x - XBLOCKS) * 256 + threadIdx.x;
        dq[i] = __float2bfloat16(wq[i]);
        dk[i] = __float2bfloat16(wk[i]);
        dp[i] = (uint8_t)__nv_cvt_float_to_fp8(wp[i], __NV_SATFINITE, __NV_E4M3);
    }
}

// ---------------------------------------------------------------------------
// lif_gate (unchanged from R9/R12).
// ---------------------------------------------------------------------------
__global__ void __launch_bounds__(512, 2) lif_gate_kernel(
    const __nv_bfloat16* __restrict__ q,
    const __nv_bfloat16* __restrict__ k,
    uint8_t* __restrict__ sp8)
{
    __shared__ float part[4][4][128];
    __shared__ uint8_t gate8[4][128];

    const int b = blockIdx.x, h = blockIdx.y;
    const int tid = threadIdx.x;
    const int c = tid >> 7, vloc = tid & 127;
    const int v = blockIdx.z * 128 + vloc;
    const int d0 = h * 128 + c * 32;

#define IDX(t, d) ((((size_t)((t) * B_ + b)) * D_ + (d)) * V_ + v)
    float qs0 = 0.f, qs1 = 0.f, qs2 = 0.f, qs3 = 0.f;
    #pragma unroll 4
    for (int j = 0; j < 32; ++j) {
        const int d = d0 + j;
        float vmq = 0.f, s;
        vmq = (vmq + __bfloat162float(q[IDX(0, d)])) * 0.5f;
        s = (vmq >= 1.f) ? 1.f : 0.f; qs0 += s; vmq *= (1.f - s);
        vmq = (vmq + __bfloat162float(q[IDX(1, d)])) * 0.5f;
        s = (vmq >= 1.f) ? 1.f : 0.f; qs1 += s; vmq *= (1.f - s);
        vmq = (vmq + __bfloat162float(q[IDX(2, d)])) * 0.5f;
        s = (vmq >= 1.f) ? 1.f : 0.f; qs2 += s; vmq *= (1.f - s);
        vmq = (vmq + __bfloat162float(q[IDX(3, d)])) * 0.5f;
        s = (vmq >= 1.f) ? 1.f : 0.f; qs3 += s;
    }
    part[c][0][vloc] = qs0; part[c][1][vloc] = qs1;
    part[c][2][vloc] = qs2; part[c][3][vloc] = qs3;
    __syncthreads();

    if (c == 0) {
        float vg = 0.f;
        #pragma unroll
        for (int t = 0; t < 4; ++t) {
            const float tot = part[0][t][vloc] + part[1][t][vloc]
                            + part[2][t][vloc] + part[3][t][vloc];
            vg = (vg + tot) * 0.5f;
            const float g = (vg >= 0.5f) ? 1.f : 0.f;
            gate8[t][vloc] = (g != 0.f) ? 0x38 : 0x00;
            vg *= (1.f - g);
        }
    }
    __syncthreads();

    const uint8_t gb0 = gate8[0][vloc], gb1 = gate8[1][vloc];
    const uint8_t gb2 = gate8[2][vloc], gb3 = gate8[3][vloc];

    #pragma unroll
    for (int half = 0; half < 2; ++half) {
        uint32_t w0[4] = {0,0,0,0}, w1[4] = {0,0,0,0}, w2[4] = {0,0,0,0}, w3[4] = {0,0,0,0};
        #pragma unroll
        for (int j = 0; j < 16; ++j) {
            const int d = d0 + half * 16 + j;
            const int wi = j >> 2, sh = (j & 3) * 8;
            float vmk = 0.f, s;
            vmk = (vmk + __bfloat162float(k[IDX(0, d)])) * 0.5f;
            s = (vmk >= 1.f) ? 1.f : 0.f;
            if (s != 0.f) w0[wi] |= (uint32_t)gb0 << sh;
            vmk *= (1.f - s);
            vmk = (vmk + __bfloat162float(k[IDX(1, d)])) * 0.5f;
            s = (vmk >= 1.f) ? 1.f : 0.f;
            if (s != 0.f) w1[wi] |= (uint32_t)gb1 << sh;
            vmk *= (1.f - s);
            vmk = (vmk + __bfloat162float(k[IDX(2, d)])) * 0.5f;
            s = (vmk >= 1.f) ? 1.f : 0.f;
            if (s != 0.f) w2[wi] |= (uint32_t)gb2 << sh;
            vmk *= (1.f - s);
            vmk = (vmk + __bfloat162float(k[IDX(3, d)])) * 0.5f;
            s = (vmk >= 1.f) ? 1.f : 0.f;
            if (s != 0.f) w3[wi] |= (uint32_t)gb3 << sh;
        }
        const size_t base = (size_t)v * D_ + d0 + half * 16;
        *(uint4*)(sp8 + (size_t)(0 * B_ + b) * V_ * D_ + base) = make_uint4(w0[0], w0[1], w0[2], w0[3]);
        *(uint4*)(sp8 + (size_t)(1 * B_ + b) * V_ * D_ + base) = make_uint4(w1[0], w1[1], w1[2], w1[3]);
        *(uint4*)(sp8 + (size_t)(2 * B_ + b) * V_ * D_ + base) = make_uint4(w2[0], w2[1], w2[2], w2[3]);
        *(uint4*)(sp8 + (size_t)(3 * B_ + b) * V_ * D_ + base) = make_uint4(w3[0], w3[1], w3[2], w3[3]);
    }
#undef IDX
}

// ---------------------------------------------------------------------------
extern "C" void kernel_launch(void* const* d_in, const int* in_sizes, int n_in,
                              void* d_out, int out_size) {
    const float* x  = (const float*)d_in[0];
    const float* Wq = (const float*)d_in[1];
    const float* qg = (const float*)d_in[2];
    const float* qb = (const float*)d_in[3];
    const float* qm = (const float*)d_in[4];
    const float* qv = (const float*)d_in[5];
    const float* Wk = (const float*)d_in[6];
    const float* kg = (const float*)d_in[7];
    const float* kb = (const float*)d_in[8];
    const float* km = (const float*)d_in[9];
    const float* kv = (const float*)d_in[10];
    const float* Wp = (const float*)d_in[11];
    const float* pg = (const float*)d_in[12];
    const float* pb = (const float*)d_in[13];
    const float* pm = (const float*)d_in[14];
    const float* pv = (const float*)d_in[15];
    float* out = (float*)d_out;

    __nv_bfloat16 *xb, *qp, *kp, *wq, *wk;
    uint8_t *sp8, *wp8;
    cudaGetSymbolAddress((void**)&xb, g_xb);
    cudaGetSymbolAddress((void**)&qp, g_qpre);
    cudaGetSymbolAddress((void**)&kp, g_kpre);
    cudaGetSymbolAddress((void**)&sp8, g_sp8);
    cudaGetSymbolAddress((void**)&wq, g_wq);
    cudaGetSymbolAddress((void**)&wk, g_wk);
    cudaGetSymbolAddress((void**)&wp8, g_wp8);

    cudaFuncSetAttribute(gemm_qk_bf16, cudaFuncAttributeMaxDynamicSharedMemorySize, SMEM_BF16);
    cudaFuncSetAttribute(gemm_fp8_lif, cudaFuncAttributeMaxDynamicSharedMemorySize, SMEM_F);

    convert_all_kernel<<<XBLOCKS + WBLOCKS, 256>>>(x, xb, Wq, Wk, Wp, wq, wk, wp8);

    gemm_qk_bf16<<<dim3(Z_, 8, 2), 256, SMEM_BF16>>>(
        wq, wk, xb, qg, qb, qm, qv, kg, kb, km, kv, qp, kp);
    lif_gate_kernel<<<dim3(B_, 4, 2), 512>>>(qp, kp, sp8);
    gemm_fp8_lif<<<dim3(B_, D_ / 128, V_ / 64), 256, SMEM_F>>>(
        wp8, sp8, pg, pb, pm, pv, out);
}

// round 15
// speedup vs baseline: 1.1394x; 1.0399x over previous
#include <cuda_runtime.h>
#include <cuda_bf16.h>
#include <cuda_fp8.h>
#include <cstdint>

#define T_ 4
#define B_ 64
#define D_ 512
#define V_ 256
#define Z_ (T_*B_)            // 256
#define PLANE (B_*D_*V_)
#define TOTAL (Z_*D_*V_)      // 33554432

// ---------------- scratch ----------------
__device__ __nv_bfloat16 g_xb[TOTAL];     // x bf16, native [z][d][v]
__device__ __nv_bfloat16 g_qpre[TOTAL];   // [z][o][v]
__device__ __nv_bfloat16 g_kpre[TOTAL];   // [z][o][v]
__device__ uint8_t       g_sp8[TOTAL];    // gate*k spikes e4m3, [z][v][d]
__device__ __nv_bfloat16 g_wq[D_*D_];
__device__ __nv_bfloat16 g_wk[D_*D_];
__device__ uint8_t       g_wp8[D_*D_];    // Wp e4m3 [o][d]

// ---------------- helpers ----------------
__device__ __forceinline__ uint32_t smem_u32(const void* p) {
    uint32_t a;
    asm("{ .reg .u64 t; cvta.to.shared.u64 t, %1; cvt.u32.u64 %0, t; }" : "=r"(a) : "l"(p));
    return a;
}
__device__ __forceinline__ void cp16(uint32_t sdst, const void* gsrc) {
    asm volatile("cp.async.cg.shared.global [%0], [%1], 16;" :: "r"(sdst), "l"(gsrc) : "memory");
}
#define CP_COMMIT() asm volatile("cp.async.commit_group;" ::: "memory")
#define CP_WAIT1()  asm volatile("cp.async.wait_group 1;" ::: "memory")
#define CP_WAIT0()  asm volatile("cp.async.wait_group 0;" ::: "memory")

__device__ __forceinline__ void ldsm_x4(uint32_t* r, uint32_t addr) {
    asm volatile("ldmatrix.sync.aligned.m8n8.x4.shared.b16 {%0,%1,%2,%3}, [%4];"
        : "=r"(r[0]), "=r"(r[1]), "=r"(r[2]), "=r"(r[3]) : "r"(addr));
}
__device__ __forceinline__ void ldsm_x4_t(uint32_t* r, uint32_t addr) {
    asm volatile("ldmatrix.sync.aligned.m8n8.x4.trans.shared.b16 {%0,%1,%2,%3}, [%4];"
        : "=r"(r[0]), "=r"(r[1]), "=r"(r[2]), "=r"(r[3]) : "r"(addr));
}
__device__ __forceinline__ void mma_bf16(float* d, const uint32_t* a, uint32_t b0, uint32_t b1) {
    asm volatile("mma.sync.aligned.m16n8k16.row.col.f32.bf16.bf16.f32 "
        "{%0,%1,%2,%3}, {%4,%5,%6,%7}, {%8,%9}, {%0,%1,%2,%3};"
        : "+f"(d[0]), "+f"(d[1]), "+f"(d[2]), "+f"(d[3])
        : "r"(a[0]), "r"(a[1]), "r"(a[2]), "r"(a[3]), "r"(b0), "r"(b1));
}
__device__ __forceinline__ void mma_fp8(float* d, const uint32_t* a, uint32_t b0, uint32_t b1) {
    asm volatile("mma.sync.aligned.m16n8k32.row.col.f32.e4m3.e4m3.f32 "
        "{%0,%1,%2,%3}, {%4,%5,%6,%7}, {%8,%9}, {%0,%1,%2,%3};"
        : "+f"(d[0]), "+f"(d[1]), "+f"(d[2]), "+f"(d[3])
        : "r"(a[0]), "r"(a[1]), "r"(a[2]), "r"(a[3]), "r"(b0), "r"(b1));
}

// ---------------------------------------------------------------------------
// Stage-1/2 GEMM (bf16) + folded BN, ONE launch for Wq+Wk.
// K-chunk = 64 (8 chunks, 64 MMAs per sync) — R12/R13 version, proven.
// ---------------------------------------------------------------------------
#define A_STG 18432            // 128 rows * 144 B
#define B_STG 17408            // 64 rows * 272 B
#define SMEM_BF16 (3*(A_STG + B_STG))   // 107520

__global__ void __launch_bounds__(256, 2) gemm_qk_bf16(
    const __nv_bfloat16* __restrict__ Wq_, const __nv_bfloat16* __restrict__ Wk_,
    const __nv_bfloat16* __restrict__ X,
    const float* __restrict__ qg, const float* __restrict__ qb,
    const float* __restrict__ qm, const float* __restrict__ qv,
    const float* __restrict__ kg, const float* __restrict__ kb,
    const float* __restrict__ km, const float* __restrict__ kv,
    __nv_bfloat16* __restrict__ Q, __nv_bfloat16* __restrict__ K)
{
    extern __shared__ __align__(16) char smem[];
    __shared__ float sScale[128], sBias[128];

    const int tid = threadIdx.x, wid = tid >> 5, lane = tid & 31;
    const int z = blockIdx.x;
    const int which = blockIdx.y >> 2;          // 0 = q, 1 = k
    const int o0 = (blockIdx.y & 3) * 128;
    const int v0 = blockIdx.z * 128;

    const __nv_bfloat16* W = which ? Wk_ : Wq_;
    const float* gamma = which ? kg : qg;
    const float* beta  = which ? kb : qb;
    const float* mean  = which ? km : qm;
    const float* var   = which ? kv : qv;
    __nv_bfloat16* O   = which ? K : Q;

    const __nv_bfloat16* Wb = W + (size_t)o0 * D_;
    const __nv_bfloat16* Xb = X + (size_t)z * D_ * V_ + v0;

    if (tid < 128) {
        const float inv = gamma[o0 + tid] * rsqrtf(var[o0 + tid] + 1e-5f);
        sScale[tid] = inv;
        sBias[tid]  = beta[o0 + tid] - mean[o0 + tid] * inv;
    }

    const uint32_t sA = smem_u32(smem);
    const uint32_t sB = sA + 3 * A_STG;
    const int wm = wid & 3, wv = wid >> 2;

    float acc[2][8][4];
    #pragma unroll
    for (int i = 0; i < 2; ++i)
        #pragma unroll
        for (int j = 0; j < 8; ++j)
            #pragma unroll
            for (int q = 0; q < 4; ++q) acc[i][j][q] = 0.f;

    auto issue = [&](int s, int kc) {
        const uint32_t ab = sA + s * A_STG;
        const uint32_t bb = sB + s * B_STG;
        #pragma unroll
        for (int i = 0; i < 4; ++i) {       // A: 128 rows x 8 x 16B
            const int idx = tid + i * 256;
            const int row = idx >> 3, c = idx & 7;
            cp16(ab + row * 144 + c * 16, Wb + (size_t)row * D_ + kc + c * 8);
        }
        #pragma unroll
        for (int i = 0; i < 4; ++i) {       // B: 64 rows x 16 x 16B
            const int idx = tid + i * 256;
            const int row = idx >> 4, c = idx & 15;
            cp16(bb + row * 272 + c * 16, Xb + (size_t)(kc + row) * V_ + c * 8);
        }
        CP_COMMIT();
    };

    issue(0, 0);
    issue(1, 64);

    #pragma unroll 1
    for (int c = 0; c < 8; ++c) {
        if (c < 7) CP_WAIT1(); else CP_WAIT0();
        __syncthreads();
        if (c < 6) issue((c + 2) % 3, (c + 2) * 64);

        const int s = c % 3;
        const uint32_t aB = sA + s * A_STG;
        const uint32_t bB = sB + s * B_STG;

        #pragma unroll
        for (int kk = 0; kk < 4; ++kk) {
            uint32_t af[2][4];
            #pragma unroll
            for (int mt = 0; mt < 2; ++mt) {
                const int row = wm * 32 + mt * 16 + (lane & 15);
                ldsm_x4(af[mt], aB + row * 144 + kk * 32 + (lane >> 4) * 16);
            }
            uint32_t bfr[4][4];
            const int sub = lane >> 3;
            const int krow = kk * 16 + (sub & 1) * 8 + (lane & 7);
            #pragma unroll
            for (int g = 0; g < 4; ++g) {
                const int ncol = wv * 64 + g * 16 + (sub >> 1) * 8;
                ldsm_x4_t(bfr[g], bB + krow * 272 + ncol * 2);
            }
            #pragma unroll
            for (int mt = 0; mt < 2; ++mt)
                #pragma unroll
                for (int g = 0; g < 4; ++g) {
                    mma_bf16(acc[mt][g * 2 + 0], af[mt], bfr[g][0], bfr[g][1]);
                    mma_bf16(acc[mt][g * 2 + 1], af[mt], bfr[g][2], bfr[g][3]);
                }
        }
    }

    #pragma unroll
    for (int mt = 0; mt < 2; ++mt) {
        const int oL = wm * 32 + mt * 16 + (lane >> 2);
        #pragma unroll
        for (int h = 0; h < 2; ++h) {
            const int o = oL + h * 8;
            const float sc = sScale[o], bi = sBias[o];
            __nv_bfloat16* orow = O + ((size_t)z * D_ + o0 + o) * V_ + v0;
            #pragma unroll
            for (int nt = 0; nt < 8; ++nt) {
                const int v = wv * 64 + nt * 8 + (lane & 3) * 2;
                const float fa = acc[mt][nt][2 * h]     * sc + bi;
                const float fb = acc[mt][nt][2 * h + 1] * sc + bi;
                const __nv_bfloat162 h2 = __floats2bfloat162_rn(fa, fb);
                *(uint32_t*)(orow + v) = *(const uint32_t*)&h2;
            }
        }
    }
}

// ---------------------------------------------------------------------------
// Fused stage-3: fp8 GEMM + BN + final LIF -> d_out fp32.
// B chunk = 256 fp8 k (8 chunks total, 64 MMAs/warp per barrier).
// A resident UNPADDED with XOR swizzle (64KB). 2-stage B ring.
// FIXED pipeline order: CP_WAIT0 -> __syncthreads -> issue(j+1) -> compute(j).
// ---------------------------------------------------------------------------
#define FA_BLK 8192                       // 128 rows * 64 B per 64-k block
#define FA_TOTAL (8*FA_BLK)               // 65536
#define FB_STG 17408                      // 64 rows * 272 B
#define SMEM_F (FA_TOTAL + 2*FB_STG)      // 100352

__global__ void __launch_bounds__(256, 2) gemm_fp8_lif(
    const uint8_t* __restrict__ W8,
    const uint8_t* __restrict__ S8,
    const float* __restrict__ gamma, const float* __restrict__ beta,
    const float* __restrict__ mean, const float* __restrict__ var,
    float* __restrict__ out)
{
    extern __shared__ __align__(16) char smem[];
    __shared__ float sScale[128], sBias[128];

    const int tid = threadIdx.x, wid = tid >> 5, lane = tid & 31;
    const int b = blockIdx.x, o0 = blockIdx.y * 128, v0 = blockIdx.z * 64;

    const uint8_t* Ab = W8 + (size_t)o0 * D_;

    if (tid < 128) {
        const float inv = gamma[o0 + tid] * rsqrtf(var[o0 + tid] + 1e-5f);
        sScale[tid] = inv;
        sBias[tid]  = beta[o0 + tid] - mean[o0 + tid] * inv;
    }

    const uint32_t sA = smem_u32(smem);
    const uint32_t sB = sA + FA_TOTAL;
    const int wm = wid & 3, wv = wid >> 2;

    // Preload entire A (Wp tile) once, XOR-swizzled, unpadded:
    // 16B unit c of row r in block blk at blk*8192 + r*64 + (c^((r>>1)&3))*16.
    #pragma unroll
    for (int i = 0; i < 16; ++i) {
        const int idx = tid + i * 256;        // 0..4095
        const int blk = idx >> 9;             // 0..7
        const int rem = idx & 511;
        const int row = rem >> 2, cc = rem & 3;
        const uint32_t sw = (uint32_t)((cc ^ ((row >> 1) & 3)) * 16);
        cp16(sA + blk * FA_BLK + row * 64 + sw,
             Ab + (size_t)row * D_ + blk * 64 + cc * 16);
    }
    CP_COMMIT();

    // B chunk j (0..7): t = j>>1, kc = (j&1)*256. 64 rows x 16 x 16B.
    auto issueB = [&](int s, int j) {
        const int t = j >> 1, kc = (j & 1) * 256;
        const uint8_t* Bb = S8 + ((size_t)(t * B_ + b) * V_ + v0) * D_;
        #pragma unroll
        for (int i = 0; i < 4; ++i) {
            const int idx = tid + i * 256;    // 0..1023
            const int row = idx >> 4, cc = idx & 15;
            cp16(sB + s * FB_STG + row * 272 + cc * 16,
                 Bb + (size_t)row * D_ + kc + cc * 16);
        }
        CP_COMMIT();
    };

    issueB(0, 0);

    float vm[2][2][4][2];   // membranes, persist across t
    #pragma unroll
    for (int i = 0; i < 2; ++i)
        #pragma unroll
        for (int j = 0; j < 2; ++j)
            #pragma unroll
            for (int q = 0; q < 4; ++q) { vm[i][j][q][0] = 0.f; vm[i][j][q][1] = 0.f; }

    float acc[2][4][4];
    #pragma unroll
    for (int i = 0; i < 2; ++i)
        #pragma unroll
        for (int j = 0; j < 4; ++j)
            #pragma unroll
            for (int q = 0; q < 4; ++q) acc[i][j][q] = 0.f;

    #pragma unroll 1
    for (int j = 0; j < 8; ++j) {
        CP_WAIT0();            // chunk j (and A on j=0) complete for this thread
        __syncthreads();       // publish copies CTA-wide; all j-1 readers done
        if (j + 1 < 8) issueB((j + 1) & 1, j + 1);   // overlaps compute below

        const uint32_t bB = sB + (j & 1) * FB_STG;
        const int ablk0 = (j & 1) * 4;         // first of four 64-k A blocks

        #pragma unroll
        for (int kk = 0; kk < 8; ++kk) {       // 8 x 32-k steps
            const uint32_t aBlk = sA + (ablk0 + (kk >> 1)) * FA_BLK;
            const int acol = (kk & 1) * 2 + (lane >> 4);   // 16B unit 0..3
            uint32_t af[2][4];
            #pragma unroll
            for (int mt = 0; mt < 2; ++mt) {
                const int row = wm * 32 + mt * 16 + (lane & 15);
                const uint32_t sw = (uint32_t)((acol ^ ((row >> 1) & 3)) * 16);
                ldsm_x4(af[mt], aBlk + row * 64 + sw);
            }
            uint32_t bfr[2][4];
            #pragma unroll
            for (int g = 0; g < 2; ++g) {
                const int row = wv * 32 + g * 16 + (lane & 15);
                ldsm_x4(bfr[g], bB + row * 272 + kk * 32 + (lane >> 4) * 16);
            }
            #pragma unroll
            for (int mt = 0; mt < 2; ++mt)
                #pragma unroll
                for (int g = 0; g < 2; ++g) {
                    mma_fp8(acc[mt][g * 2 + 0], af[mt], bfr[g][0], bfr[g][2]);
                    mma_fp8(acc[mt][g * 2 + 1], af[mt], bfr[g][1], bfr[g][3]);
                }
        }

        if ((j & 1) == 1) {
            // end of timestep t: BN + LIF + store, reset acc
            const int t = j >> 1;
            const size_t zofs = (size_t)(t * B_ + b) * D_;
            #pragma unroll
            for (int mt = 0; mt < 2; ++mt) {
                const int oL = wm * 32 + mt * 16 + (lane >> 2);
                #pragma unroll
                for (int h = 0; h < 2; ++h) {
                    const int o = oL + h * 8;
                    const float sc = sScale[o], bi = sBias[o];
                    float* orow = out + (zofs + o0 + o) * V_ + v0;
                    #pragma unroll
                    for (int nt = 0; nt < 4; ++nt) {
                        const int v = wv * 32 + nt * 8 + (lane & 3) * 2;
                        const float f0 = acc[mt][nt][2 * h]     * sc + bi;
                        const float f1 = acc[mt][nt][2 * h + 1] * sc + bi;
                        float m0 = (vm[mt][h][nt][0] + f0) * 0.5f;
                        float m1 = (vm[mt][h][nt][1] + f1) * 0.5f;
                        const float s0 = (m0 >= 1.f) ? 1.f : 0.f;
                        const float s1 = (m1 >= 1.f) ? 1.f : 0.f;
                        vm[mt][h][nt][0] = m0 * (1.f - s0);
                        vm[mt][h][nt][1] = m1 * (1.f - s1);
                        *(float2*)(orow + v) = make_float2(s0, s1);
                        acc[mt][nt][2 * h] = 0.f;
                        acc[mt][nt][2 * h + 1] = 0.f;
                    }
                }
            }
        }
    }
}

// ---------------------------------------------------------------------------
// Single converter launch (unchanged).
// ---------------------------------------------------------------------------
#define XBLOCKS (TOTAL / 1024)
#define WBLOCKS (D_ * D_ / 256)

__global__ void convert_all_kernel(
    const float* __restrict__ x, __nv_bfloat16* __restrict__ xb,
    const float* __restrict__ wq, const float* __restrict__ wk,
    const float* __restrict__ wp,
    __nv_bfloat16* __restrict__ dq, __nv_bfloat16* __restrict__ dk,
    uint8_t* __restrict__ dp)
{
    if (blockIdx.x < XBLOCKS) {
        const size_t i = (size_t)blockIdx.x * 256 + threadIdx.x;
        const float4 f = ((const float4*)x)[i];
        const __nv_bfloat162 a = __floats2bfloat162_rn(f.x, f.y);
        const __nv_bfloat162 b = __floats2bfloat162_rn(f.z, f.w);
        uint2 u;
        u.x = *(const uint32_t*)&a;
        u.y = *(const uint32_t*)&b;
        ((uint2*)xb)[i] = u;
    } else {
        const int i = (blockIdx.x - XBLOCKS) * 256 + threadIdx.x;
        dq[i] = __float2bfloat16(wq[i]);
        dk[i] = __float2bfloat16(wk[i]);
        dp[i] = (uint8_t)__nv_cvt_float_to_fp8(wp[i], __NV_SATFINITE, __NV_E4M3);
    }
}

// ---------------------------------------------------------------------------
// lif_gate (unchanged from R9/R12/R13).
// ---------------------------------------------------------------------------
__global__ void __launch_bounds__(512, 2) lif_gate_kernel(
    const __nv_bfloat16* __restrict__ q,
    const __nv_bfloat16* __restrict__ k,
    uint8_t* __restrict__ sp8)
{
    __shared__ float part[4][4][128];
    __shared__ uint8_t gate8[4][128];

    const int b = blockIdx.x, h = blockIdx.y;
    const int tid = threadIdx.x;
    const int c = tid >> 7, vloc = tid & 127;
    const int v = blockIdx.z * 128 + vloc;
    const int d0 = h * 128 + c * 32;

#define IDX(t, d) ((((size_t)((t) * B_ + b)) * D_ + (d)) * V_ + v)
    float qs0 = 0.f, qs1 = 0.f, qs2 = 0.f, qs3 = 0.f;
    #pragma unroll 4
    for (int j = 0; j < 32; ++j) {
        const int d = d0 + j;
        float vmq = 0.f, s;
        vmq = (vmq + __bfloat162float(q[IDX(0, d)])) * 0.5f;
        s = (vmq >= 1.f) ? 1.f : 0.f; qs0 += s; vmq *= (1.f - s);
        vmq = (vmq + __bfloat162float(q[IDX(1, d)])) * 0.5f;
        s = (vmq >= 1.f) ? 1.f : 0.f; qs1 += s; vmq *= (1.f - s);
        vmq = (vmq + __bfloat162float(q[IDX(2, d)])) * 0.5f;
        s = (vmq >= 1.f) ? 1.f : 0.f; qs2 += s; vmq *= (1.f - s);
        vmq = (vmq + __bfloat162float(q[IDX(3, d)])) * 0.5f;
        s = (vmq >= 1.f) ? 1.f : 0.f; qs3 += s;
    }
    part[c][0][vloc] = qs0; part[c][1][vloc] = qs1;
    part[c][2][vloc] = qs2; part[c][3][vloc] = qs3;
    __syncthreads();

    if (c == 0) {
        float vg = 0.f;
        #pragma unroll
        for (int t = 0; t < 4; ++t) {
            const float tot = part[0][t][vloc] + part[1][t][vloc]
                            + part[2][t][vloc] + part[3][t][vloc];
            vg = (vg + tot) * 0.5f;
            const float g = (vg >= 0.5f) ? 1.f : 0.f;
            gate8[t][vloc] = (g != 0.f) ? 0x38 : 0x00;
            vg *= (1.f - g);
        }
    }
    __syncthreads();

    const uint8_t gb0 = gate8[0][vloc], gb1 = gate8[1][vloc];
    const uint8_t gb2 = gate8[2][vloc], gb3 = gate8[3][vloc];

    #pragma unroll
    for (int half = 0; half < 2; ++half) {
        uint32_t w0[4] = {0,0,0,0}, w1[4] = {0,0,0,0}, w2[4] = {0,0,0,0}, w3[4] = {0,0,0,0};
        #pragma unroll
        for (int j = 0; j < 16; ++j) {
            const int d = d0 + half * 16 + j;
            const int wi = j >> 2, sh = (j & 3) * 8;
            float vmk = 0.f, s;
            vmk = (vmk + __bfloat162float(k[IDX(0, d)])) * 0.5f;
            s = (vmk >= 1.f) ? 1.f : 0.f;
            if (s != 0.f) w0[wi] |= (uint32_t)gb0 << sh;
            vmk *= (1.f - s);
            vmk = (vmk + __bfloat162float(k[IDX(1, d)])) * 0.5f;
            s = (vmk >= 1.f) ? 1.f : 0.f;
            if (s != 0.f) w1[wi] |= (uint32_t)gb1 << sh;
            vmk *= (1.f - s);
            vmk = (vmk + __bfloat162float(k[IDX(2, d)])) * 0.5f;
            s = (vmk >= 1.f) ? 1.f : 0.f;
            if (s != 0.f) w2[wi] |= (uint32_t)gb2 << sh;
            vmk *= (1.f - s);
            vmk = (vmk + __bfloat162float(k[IDX(3, d)])) * 0.5f;
            s = (vmk >= 1.f) ? 1.f : 0.f;
            if (s != 0.f) w3[wi] |= (uint32_t)gb3 << sh;
        }
        const size_t base = (size_t)v * D_ + d0 + half * 16;
        *(uint4*)(sp8 + (size_t)(0 * B_ + b) * V_ * D_ + base) = make_uint4(w0[0], w0[1], w0[2], w0[3]);
        *(uint4*)(sp8 + (size_t)(1 * B_ + b) * V_ * D_ + base) = make_uint4(w1[0], w1[1], w1[2], w1[3]);
        *(uint4*)(sp8 + (size_t)(2 * B_ + b) * V_ * D_ + base) = make_uint4(w2[0], w2[1], w2[2], w2[3]);
        *(uint4*)(sp8 + (size_t)(3 * B_ + b) * V_ * D_ + base) = make_uint4(w3[0], w3[1], w3[2], w3[3]);
    }
#undef IDX
}

// ---------------------------------------------------------------------------
extern "C" void kernel_launch(void* const* d_in, const int* in_sizes, int n_in,
                              void* d_out, int out_size) {
    const float* x  = (const float*)d_in[0];
    const float* Wq = (const float*)d_in[1];
    const float* qg = (const float*)d_in[2];
    const float* qb = (const float*)d_in[3];
    const float* qm = (const float*)d_in[4];
    const float* qv = (const float*)d_in[5];
    const float* Wk = (const float*)d_in[6];
    const float* kg = (const float*)d_in[7];
    const float* kb = (const float*)d_in[8];
    const float* km = (const float*)d_in[9];
    const float* kv = (const float*)d_in[10];
    const float* Wp = (const float*)d_in[11];
    const float* pg = (const float*)d_in[12];
    const float* pb = (const float*)d_in[13];
    const float* pm = (const float*)d_in[14];
    const float* pv = (const float*)d_in[15];
    float* out = (float*)d_out;

    __nv_bfloat16 *xb, *qp, *kp, *wq, *wk;
    uint8_t *sp8, *wp8;
    cudaGetSymbolAddress((void**)&xb, g_xb);
    cudaGetSymbolAddress((void**)&qp, g_qpre);
    cudaGetSymbolAddress((void**)&kp, g_kpre);
    cudaGetSymbolAddress((void**)&sp8, g_sp8);
    cudaGetSymbolAddress((void**)&wq, g_wq);
    cudaGetSymbolAddress((void**)&wk, g_wk);
    cudaGetSymbolAddress((void**)&wp8, g_wp8);

    cudaFuncSetAttribute(gemm_qk_bf16, cudaFuncAttributeMaxDynamicSharedMemorySize, SMEM_BF16);
    cudaFuncSetAttribute(gemm_fp8_lif, cudaFuncAttributeMaxDynamicSharedMemorySize, SMEM_F);

    convert_all_kernel<<<XBLOCKS + WBLOCKS, 256>>>(x, xb, Wq, Wk, Wp, wq, wk, wp8);

    gemm_qk_bf16<<<dim3(Z_, 8, 2), 256, SMEM_BF16>>>(
        wq, wk, xb, qg, qb, qm, qv, kg, kb, km, kv, qp, kp);
    lif_gate_kernel<<<dim3(B_, 4, 2), 512>>>(qp, kp, sp8);
    gemm_fp8_lif<<<dim3(B_, D_ / 128, V_ / 64), 256, SMEM_F>>>(
        wp8, sp8, pg, pb, pm, pv, out);
}

// round 16
// speedup vs baseline: 1.1759x; 1.0320x over previous
#include <cuda_runtime.h>
#include <cuda_bf16.h>
#include <cuda_fp8.h>
#include <cstdint>

#define T_ 4
#define B_ 64
#define D_ 512
#define V_ 256
#define Z_ (T_*B_)            // 256
#define PLANE (B_*D_*V_)
#define TOTAL (Z_*D_*V_)      // 33554432

// ---------------- scratch ----------------
__device__ __nv_bfloat16 g_xb[TOTAL];     // x bf16, native [z][d][v]
__device__ __nv_bfloat16 g_qpre[TOTAL];   // [z][o][v]
__device__ __nv_bfloat16 g_kpre[TOTAL];   // [z][o][v]
__device__ uint8_t       g_sp8[TOTAL];    // gate*k spikes e4m3, [z][v][d]
__device__ __nv_bfloat16 g_wq[D_*D_];
__device__ __nv_bfloat16 g_wk[D_*D_];
__device__ uint8_t       g_wp8[D_*D_];    // Wp e4m3 [o][d]

// ---------------- helpers ----------------
__device__ __forceinline__ uint32_t smem_u32(const void* p) {
    uint32_t a;
    asm("{ .reg .u64 t; cvta.to.shared.u64 t, %1; cvt.u32.u64 %0, t; }" : "=r"(a) : "l"(p));
    return a;
}
__device__ __forceinline__ void cp16(uint32_t sdst, const void* gsrc) {
    asm volatile("cp.async.cg.shared.global [%0], [%1], 16;" :: "r"(sdst), "l"(gsrc) : "memory");
}
#define CP_COMMIT() asm volatile("cp.async.commit_group;" ::: "memory")
#define CP_WAIT1()  asm volatile("cp.async.wait_group 1;" ::: "memory")
#define CP_WAIT0()  asm volatile("cp.async.wait_group 0;" ::: "memory")

__device__ __forceinline__ void ldsm_x4(uint32_t* r, uint32_t addr) {
    asm volatile("ldmatrix.sync.aligned.m8n8.x4.shared.b16 {%0,%1,%2,%3}, [%4];"
        : "=r"(r[0]), "=r"(r[1]), "=r"(r[2]), "=r"(r[3]) : "r"(addr));
}
__device__ __forceinline__ void ldsm_x4_t(uint32_t* r, uint32_t addr) {
    asm volatile("ldmatrix.sync.aligned.m8n8.x4.trans.shared.b16 {%0,%1,%2,%3}, [%4];"
        : "=r"(r[0]), "=r"(r[1]), "=r"(r[2]), "=r"(r[3]) : "r"(addr));
}
__device__ __forceinline__ void mma_bf16(float* d, const uint32_t* a, uint32_t b0, uint32_t b1) {
    asm volatile("mma.sync.aligned.m16n8k16.row.col.f32.bf16.bf16.f32 "
        "{%0,%1,%2,%3}, {%4,%5,%6,%7}, {%8,%9}, {%0,%1,%2,%3};"
        : "+f"(d[0]), "+f"(d[1]), "+f"(d[2]), "+f"(d[3])
        : "r"(a[0]), "r"(a[1]), "r"(a[2]), "r"(a[3]), "r"(b0), "r"(b1));
}
__device__ __forceinline__ void mma_fp8(float* d, const uint32_t* a, uint32_t b0, uint32_t b1) {
    asm volatile("mma.sync.aligned.m16n8k32.row.col.f32.e4m3.e4m3.f32 "
        "{%0,%1,%2,%3}, {%4,%5,%6,%7}, {%8,%9}, {%0,%1,%2,%3};"
        : "+f"(d[0]), "+f"(d[1]), "+f"(d[2]), "+f"(d[3])
        : "r"(a[0]), "r"(a[1]), "r"(a[2]), "r"(a[3]), "r"(b0), "r"(b1));
}
// streaming bf16 load (read-once data; bypass L2 persistence)
__device__ __forceinline__ float ldcs_bf16(const __nv_bfloat16* p) {
    const unsigned short u = __ldcs((const unsigned short*)p);
    __nv_bfloat16 h;
    *reinterpret_cast<unsigned short*>(&h) = u;
    return __bfloat162float(h);
}

// ---------------------------------------------------------------------------
// Stage-1/2 GEMM (bf16) + folded BN, ONE launch for Wq+Wk.
// K-chunk = 64 (8 chunks, 64 MMAs per sync) — R12/R13/R15 version, proven.
// ---------------------------------------------------------------------------
#define A_STG 18432            // 128 rows * 144 B
#define B_STG 17408            // 64 rows * 272 B
#define SMEM_BF16 (3*(A_STG + B_STG))   // 107520

__global__ void __launch_bounds__(256, 2) gemm_qk_bf16(
    const __nv_bfloat16* __restrict__ Wq_, const __nv_bfloat16* __restrict__ Wk_,
    const __nv_bfloat16* __restrict__ X,
    const float* __restrict__ qg, const float* __restrict__ qb,
    const float* __restrict__ qm, const float* __restrict__ qv,
    const float* __restrict__ kg, const float* __restrict__ kb,
    const float* __restrict__ km, const float* __restrict__ kv,
    __nv_bfloat16* __restrict__ Q, __nv_bfloat16* __restrict__ K)
{
    extern __shared__ __align__(16) char smem[];
    __shared__ float sScale[128], sBias[128];

    const int tid = threadIdx.x, wid = tid >> 5, lane = tid & 31;
    const int z = blockIdx.x;
    const int which = blockIdx.y >> 2;          // 0 = q, 1 = k
    const int o0 = (blockIdx.y & 3) * 128;
    const int v0 = blockIdx.z * 128;

    const __nv_bfloat16* W = which ? Wk_ : Wq_;
    const float* gamma = which ? kg : qg;
    const float* beta  = which ? kb : qb;
    const float* mean  = which ? km : qm;
    const float* var   = which ? kv : qv;
    __nv_bfloat16* O   = which ? K : Q;

    const __nv_bfloat16* Wb = W + (size_t)o0 * D_;
    const __nv_bfloat16* Xb = X + (size_t)z * D_ * V_ + v0;

    if (tid < 128) {
        const float inv = gamma[o0 + tid] * rsqrtf(var[o0 + tid] + 1e-5f);
        sScale[tid] = inv;
        sBias[tid]  = beta[o0 + tid] - mean[o0 + tid] * inv;
    }

    const uint32_t sA = smem_u32(smem);
    const uint32_t sB = sA + 3 * A_STG;
    const int wm = wid & 3, wv = wid >> 2;

    float acc[2][8][4];
    #pragma unroll
    for (int i = 0; i < 2; ++i)
        #pragma unroll
        for (int j = 0; j < 8; ++j)
            #pragma unroll
            for (int q = 0; q < 4; ++q) acc[i][j][q] = 0.f;

    auto issue = [&](int s, int kc) {
        const uint32_t ab = sA + s * A_STG;
        const uint32_t bb = sB + s * B_STG;
        #pragma unroll
        for (int i = 0; i < 4; ++i) {       // A: 128 rows x 8 x 16B
            const int idx = tid + i * 256;
            const int row = idx >> 3, c = idx & 7;
            cp16(ab + row * 144 + c * 16, Wb + (size_t)row * D_ + kc + c * 8);
        }
        #pragma unroll
        for (int i = 0; i < 4; ++i) {       // B: 64 rows x 16 x 16B
            const int idx = tid + i * 256;
            const int row = idx >> 4, c = idx & 15;
            cp16(bb + row * 272 + c * 16, Xb + (size_t)(kc + row) * V_ + c * 8);
        }
        CP_COMMIT();
    };

    issue(0, 0);
    issue(1, 64);

    #pragma unroll 1
    for (int c = 0; c < 8; ++c) {
        if (c < 7) CP_WAIT1(); else CP_WAIT0();
        __syncthreads();
        if (c < 6) issue((c + 2) % 3, (c + 2) * 64);

        const int s = c % 3;
        const uint32_t aB = sA + s * A_STG;
        const uint32_t bB = sB + s * B_STG;

        #pragma unroll
        for (int kk = 0; kk < 4; ++kk) {
            uint32_t af[2][4];
            #pragma unroll
            for (int mt = 0; mt < 2; ++mt) {
                const int row = wm * 32 + mt * 16 + (lane & 15);
                ldsm_x4(af[mt], aB + row * 144 + kk * 32 + (lane >> 4) * 16);
            }
            uint32_t bfr[4][4];
            const int sub = lane >> 3;
            const int krow = kk * 16 + (sub & 1) * 8 + (lane & 7);
            #pragma unroll
            for (int g = 0; g < 4; ++g) {
                const int ncol = wv * 64 + g * 16 + (sub >> 1) * 8;
                ldsm_x4_t(bfr[g], bB + krow * 272 + ncol * 2);
            }
            #pragma unroll
            for (int mt = 0; mt < 2; ++mt)
                #pragma unroll
                for (int g = 0; g < 4; ++g) {
                    mma_bf16(acc[mt][g * 2 + 0], af[mt], bfr[g][0], bfr[g][1]);
                    mma_bf16(acc[mt][g * 2 + 1], af[mt], bfr[g][2], bfr[g][3]);
                }
        }
    }

    #pragma unroll
    for (int mt = 0; mt < 2; ++mt) {
        const int oL = wm * 32 + mt * 16 + (lane >> 2);
        #pragma unroll
        for (int h = 0; h < 2; ++h) {
            const int o = oL + h * 8;
            const float sc = sScale[o], bi = sBias[o];
            __nv_bfloat16* orow = O + ((size_t)z * D_ + o0 + o) * V_ + v0;
            #pragma unroll
            for (int nt = 0; nt < 8; ++nt) {
                const int v = wv * 64 + nt * 8 + (lane & 3) * 2;
                const float fa = acc[mt][nt][2 * h]     * sc + bi;
                const float fb = acc[mt][nt][2 * h + 1] * sc + bi;
                const __nv_bfloat162 h2 = __floats2bfloat162_rn(fa, fb);
                *(uint32_t*)(orow + v) = *(const uint32_t*)&h2;
            }
        }
    }
}

// ---------------------------------------------------------------------------
// Fused stage-3: fp8 GEMM + BN + final LIF -> d_out fp32 (R15 version).
// B chunk = 256 fp8 k (8 chunks, 64 MMAs/warp per barrier), A resident
// XOR-swizzled, 2-stage B ring; wait0 -> sync -> issue -> compute order.
// Output stores use __stcs (never re-read on device).
// ---------------------------------------------------------------------------
#define FA_BLK 8192                       // 128 rows * 64 B per 64-k block
#define FA_TOTAL (8*FA_BLK)               // 65536
#define FB_STG 17408                      // 64 rows * 272 B
#define SMEM_F (FA_TOTAL + 2*FB_STG)      // 100352

__global__ void __launch_bounds__(256, 2) gemm_fp8_lif(
    const uint8_t* __restrict__ W8,
    const uint8_t* __restrict__ S8,
    const float* __restrict__ gamma, const float* __restrict__ beta,
    const float* __restrict__ mean, const float* __restrict__ var,
    float* __restrict__ out)
{
    extern __shared__ __align__(16) char smem[];
    __shared__ float sScale[128], sBias[128];

    const int tid = threadIdx.x, wid = tid >> 5, lane = tid & 31;
    const int b = blockIdx.x, o0 = blockIdx.y * 128, v0 = blockIdx.z * 64;

    const uint8_t* Ab = W8 + (size_t)o0 * D_;

    if (tid < 128) {
        const float inv = gamma[o0 + tid] * rsqrtf(var[o0 + tid] + 1e-5f);
        sScale[tid] = inv;
        sBias[tid]  = beta[o0 + tid] - mean[o0 + tid] * inv;
    }

    const uint32_t sA = smem_u32(smem);
    const uint32_t sB = sA + FA_TOTAL;
    const int wm = wid & 3, wv = wid >> 2;

    // Preload entire A (Wp tile) once, XOR-swizzled, unpadded.
    #pragma unroll
    for (int i = 0; i < 16; ++i) {
        const int idx = tid + i * 256;        // 0..4095
        const int blk = idx >> 9;             // 0..7
        const int rem = idx & 511;
        const int row = rem >> 2, cc = rem & 3;
        const uint32_t sw = (uint32_t)((cc ^ ((row >> 1) & 3)) * 16);
        cp16(sA + blk * FA_BLK + row * 64 + sw,
             Ab + (size_t)row * D_ + blk * 64 + cc * 16);
    }
    CP_COMMIT();

    auto issueB = [&](int s, int j) {
        const int t = j >> 1, kc = (j & 1) * 256;
        const uint8_t* Bb = S8 + ((size_t)(t * B_ + b) * V_ + v0) * D_;
        #pragma unroll
        for (int i = 0; i < 4; ++i) {
            const int idx = tid + i * 256;    // 0..1023
            const int row = idx >> 4, cc = idx & 15;
            cp16(sB + s * FB_STG + row * 272 + cc * 16,
                 Bb + (size_t)row * D_ + kc + cc * 16);
        }
        CP_COMMIT();
    };

    issueB(0, 0);

    float vm[2][2][4][2];
    #pragma unroll
    for (int i = 0; i < 2; ++i)
        #pragma unroll
        for (int j = 0; j < 2; ++j)
            #pragma unroll
            for (int q = 0; q < 4; ++q) { vm[i][j][q][0] = 0.f; vm[i][j][q][1] = 0.f; }

    float acc[2][4][4];
    #pragma unroll
    for (int i = 0; i < 2; ++i)
        #pragma unroll
        for (int j = 0; j < 4; ++j)
            #pragma unroll
            for (int q = 0; q < 4; ++q) acc[i][j][q] = 0.f;

    #pragma unroll 1
    for (int j = 0; j < 8; ++j) {
        CP_WAIT0();
        __syncthreads();
        if (j + 1 < 8) issueB((j + 1) & 1, j + 1);

        const uint32_t bB = sB + (j & 1) * FB_STG;
        const int ablk0 = (j & 1) * 4;

        #pragma unroll
        for (int kk = 0; kk < 8; ++kk) {
            const uint32_t aBlk = sA + (ablk0 + (kk >> 1)) * FA_BLK;
            const int acol = (kk & 1) * 2 + (lane >> 4);
            uint32_t af[2][4];
            #pragma unroll
            for (int mt = 0; mt < 2; ++mt) {
                const int row = wm * 32 + mt * 16 + (lane & 15);
                const uint32_t sw = (uint32_t)((acol ^ ((row >> 1) & 3)) * 16);
                ldsm_x4(af[mt], aBlk + row * 64 + sw);
            }
            uint32_t bfr[2][4];
            #pragma unroll
            for (int g = 0; g < 2; ++g) {
                const int row = wv * 32 + g * 16 + (lane & 15);
                ldsm_x4(bfr[g], bB + row * 272 + kk * 32 + (lane >> 4) * 16);
            }
            #pragma unroll
            for (int mt = 0; mt < 2; ++mt)
                #pragma unroll
                for (int g = 0; g < 2; ++g) {
                    mma_fp8(acc[mt][g * 2 + 0], af[mt], bfr[g][0], bfr[g][2]);
                    mma_fp8(acc[mt][g * 2 + 1], af[mt], bfr[g][1], bfr[g][3]);
                }
        }

        if ((j & 1) == 1) {
            const int t = j >> 1;
            const size_t zofs = (size_t)(t * B_ + b) * D_;
            #pragma unroll
            for (int mt = 0; mt < 2; ++mt) {
                const int oL = wm * 32 + mt * 16 + (lane >> 2);
                #pragma unroll
                for (int h = 0; h < 2; ++h) {
                    const int o = oL + h * 8;
                    const float sc = sScale[o], bi = sBias[o];
                    float* orow = out + (zofs + o0 + o) * V_ + v0;
                    #pragma unroll
                    for (int nt = 0; nt < 4; ++nt) {
                        const int v = wv * 32 + nt * 8 + (lane & 3) * 2;
                        const float f0 = acc[mt][nt][2 * h]     * sc + bi;
                        const float f1 = acc[mt][nt][2 * h + 1] * sc + bi;
                        float m0 = (vm[mt][h][nt][0] + f0) * 0.5f;
                        float m1 = (vm[mt][h][nt][1] + f1) * 0.5f;
                        const float s0 = (m0 >= 1.f) ? 1.f : 0.f;
                        const float s1 = (m1 >= 1.f) ? 1.f : 0.f;
                        vm[mt][h][nt][0] = m0 * (1.f - s0);
                        vm[mt][h][nt][1] = m1 * (1.f - s1);
                        __stcs((float2*)(orow + v), make_float2(s0, s1));
                        acc[mt][nt][2 * h] = 0.f;
                        acc[mt][nt][2 * h + 1] = 0.f;
                    }
                }
            }
        }
    }
}

// ---------------------------------------------------------------------------
// Single converter launch. x-path: 2x float4 per thread, streaming loads,
// one 16B store of 8 packed bf16.
// ---------------------------------------------------------------------------
#define XBLOCKS (TOTAL / 2048)           // 16384 (8 elems/thread)
#define WBLOCKS (D_ * D_ / 256)          // 1024

__global__ void convert_all_kernel(
    const float* __restrict__ x, __nv_bfloat16* __restrict__ xb,
    const float* __restrict__ wq, const float* __restrict__ wk,
    const float* __restrict__ wp,
    __nv_bfloat16* __restrict__ dq, __nv_bfloat16* __restrict__ dk,
    uint8_t* __restrict__ dp)
{
    if (blockIdx.x < XBLOCKS) {
        const size_t i = (size_t)blockIdx.x * 256 + threadIdx.x;   // uint4 index
        const float4 fa = __ldcs(((const float4*)x) + 2 * i);
        const float4 fb = __ldcs(((const float4*)x) + 2 * i + 1);
        const __nv_bfloat162 p0 = __floats2bfloat162_rn(fa.x, fa.y);
        const __nv_bfloat162 p1 = __floats2bfloat162_rn(fa.z, fa.w);
        const __nv_bfloat162 p2 = __floats2bfloat162_rn(fb.x, fb.y);
        const __nv_bfloat162 p3 = __floats2bfloat162_rn(fb.z, fb.w);
        uint4 u;
        u.x = *(const uint32_t*)&p0;
        u.y = *(const uint32_t*)&p1;
        u.z = *(const uint32_t*)&p2;
        u.w = *(const uint32_t*)&p3;
        ((uint4*)xb)[i] = u;
    } else {
        const int i = (blockIdx.x - XBLOCKS) * 256 + threadIdx.x;
        dq[i] = __float2bfloat16(wq[i]);
        dk[i] = __float2bfloat16(wk[i]);
        dp[i] = (uint8_t)__nv_cvt_float_to_fp8(wp[i], __NV_SATFINITE, __NV_E4M3);
    }
}

// ---------------------------------------------------------------------------
// lif_gate: LIF(q) -> q_sum -> gate LIF(0.5) -> LIF(k) -> sp8 [z][v][d].
// R9 structure; q/k reads via __ldcs (read-once).
// ---------------------------------------------------------------------------
__global__ void __launch_bounds__(512, 2) lif_gate_kernel(
    const __nv_bfloat16* __restrict__ q,
    const __nv_bfloat16* __restrict__ k,
    uint8_t* __restrict__ sp8)
{
    __shared__ float part[4][4][128];
    __shared__ uint8_t gate8[4][128];

    const int b = blockIdx.x, h = blockIdx.y;
    const int tid = threadIdx.x;
    const int c = tid >> 7, vloc = tid & 127;
    const int v = blockIdx.z * 128 + vloc;
    const int d0 = h * 128 + c * 32;

#define IDX(t, d) ((((size_t)((t) * B_ + b)) * D_ + (d)) * V_ + v)
    float qs0 = 0.f, qs1 = 0.f, qs2 = 0.f, qs3 = 0.f;
    #pragma unroll 4
    for (int j = 0; j < 32; ++j) {
        const int d = d0 + j;
        float vmq = 0.f, s;
        vmq = (vmq + ldcs_bf16(q + IDX(0, d))) * 0.5f;
        s = (vmq >= 1.f) ? 1.f : 0.f; qs0 += s; vmq *= (1.f - s);
        vmq = (vmq + ldcs_bf16(q + IDX(1, d))) * 0.5f;
        s = (vmq >= 1.f) ? 1.f : 0.f; qs1 += s; vmq *= (1.f - s);
        vmq = (vmq + ldcs_bf16(q + IDX(2, d))) * 0.5f;
        s = (vmq >= 1.f) ? 1.f : 0.f; qs2 += s; vmq *= (1.f - s);
        vmq = (vmq + ldcs_bf16(q + IDX(3, d))) * 0.5f;
        s = (vmq >= 1.f) ? 1.f : 0.f; qs3 += s;
    }
    part[c][0][vloc] = qs0; part[c][1][vloc] = qs1;
    part[c][2][vloc] = qs2; part[c][3][vloc] = qs3;
    __syncthreads();

    if (c == 0) {
        float vg = 0.f;
        #pragma unroll
        for (int t = 0; t < 4; ++t) {
            const float tot = part[0][t][vloc] + part[1][t][vloc]
                            + part[2][t][vloc] + part[3][t][vloc];
            vg = (vg + tot) * 0.5f;
            const float g = (vg >= 0.5f) ? 1.f : 0.f;
            gate8[t][vloc] = (g != 0.f) ? 0x38 : 0x00;
            vg *= (1.f - g);
        }
    }
    __syncthreads();

    const uint8_t gb0 = gate8[0][vloc], gb1 = gate8[1][vloc];
    const uint8_t gb2 = gate8[2][vloc], gb3 = gate8[3][vloc];

    #pragma unroll
    for (int half = 0; half < 2; ++half) {
        uint32_t w0[4] = {0,0,0,0}, w1[4] = {0,0,0,0}, w2[4] = {0,0,0,0}, w3[4] = {0,0,0,0};
        #pragma unroll
        for (int j = 0; j < 16; ++j) {
            const int d = d0 + half * 16 + j;
            const int wi = j >> 2, sh = (j & 3) * 8;
            float vmk = 0.f, s;
            vmk = (vmk + ldcs_bf16(k + IDX(0, d))) * 0.5f;
            s = (vmk >= 1.f) ? 1.f : 0.f;
            if (s != 0.f) w0[wi] |= (uint32_t)gb0 << sh;
            vmk *= (1.f - s);
            vmk = (vmk + ldcs_bf16(k + IDX(1, d))) * 0.5f;
            s = (vmk >= 1.f) ? 1.f : 0.f;
            if (s != 0.f) w1[wi] |= (uint32_t)gb1 << sh;
            vmk *= (1.f - s);
            vmk = (vmk + ldcs_bf16(k + IDX(2, d))) * 0.5f;
            s = (vmk >= 1.f) ? 1.f : 0.f;
            if (s != 0.f) w2[wi] |= (uint32_t)gb2 << sh;
            vmk *= (1.f - s);
            vmk = (vmk + ldcs_bf16(k + IDX(3, d))) * 0.5f;
            s = (vmk >= 1.f) ? 1.f : 0.f;
            if (s != 0.f) w3[wi] |= (uint32_t)gb3 << sh;
        }
        const size_t base = (size_t)v * D_ + d0 + half * 16;
        *(uint4*)(sp8 + (size_t)(0 * B_ + b) * V_ * D_ + base) = make_uint4(w0[0], w0[1], w0[2], w0[3]);
        *(uint4*)(sp8 + (size_t)(1 * B_ + b) * V_ * D_ + base) = make_uint4(w1[0], w1[1], w1[2], w1[3]);
        *(uint4*)(sp8 + (size_t)(2 * B_ + b) * V_ * D_ + base) = make_uint4(w2[0], w2[1], w2[2], w2[3]);
        *(uint4*)(sp8 + (size_t)(3 * B_ + b) * V_ * D_ + base) = make_uint4(w3[0], w3[1], w3[2], w3[3]);
    }
#undef IDX
}

// ---------------------------------------------------------------------------
extern "C" void kernel_launch(void* const* d_in, const int* in_sizes, int n_in,
                              void* d_out, int out_size) {
    const float* x  = (const float*)d_in[0];
    const float* Wq = (const float*)d_in[1];
    const float* qg = (const float*)d_in[2];
    const float* qb = (const float*)d_in[3];
    const float* qm = (const float*)d_in[4];
    const float* qv = (const float*)d_in[5];
    const float* Wk = (const float*)d_in[6];
    const float* kg = (const float*)d_in[7];
    const float* kb = (const float*)d_in[8];
    const float* km = (const float*)d_in[9];
    const float* kv = (const float*)d_in[10];
    const float* Wp = (const float*)d_in[11];
    const float* pg = (const float*)d_in[12];
    const float* pb = (const float*)d_in[13];
    const float* pm = (const float*)d_in[14];
    const float* pv = (const float*)d_in[15];
    float* out = (float*)d_out;

    __nv_bfloat16 *xb, *qp, *kp, *wq, *wk;
    uint8_t *sp8, *wp8;
    cudaGetSymbolAddress((void**)&xb, g_xb);
    cudaGetSymbolAddress((void**)&qp, g_qpre);
    cudaGetSymbolAddress((void**)&kp, g_kpre);
    cudaGetSymbolAddress((void**)&sp8, g_sp8);
    cudaGetSymbolAddress((void**)&wq, g_wq);
    cudaGetSymbolAddress((void**)&wk, g_wk);
    cudaGetSymbolAddress((void**)&wp8, g_wp8);

    cudaFuncSetAttribute(gemm_qk_bf16, cudaFuncAttributeMaxDynamicSharedMemorySize, SMEM_BF16);
    cudaFuncSetAttribute(gemm_fp8_lif, cudaFuncAttributeMaxDynamicSharedMemorySize, SMEM_F);

    convert_all_kernel<<<XBLOCKS + WBLOCKS, 256>>>(x, xb, Wq, Wk, Wp, wq, wk, wp8);

    gemm_qk_bf16<<<dim3(Z_, 8, 2), 256, SMEM_BF16>>>(
        wq, wk, xb, qg, qb, qm, qv, kg, kb, km, kv, qp, kp);
    lif_gate_kernel<<<dim3(B_, 4, 2), 512>>>(qp, kp, sp8);
    gemm_fp8_lif<<<dim3(B_, D_ / 128, V_ / 64), 256, SMEM_F>>>(
        wp8, sp8, pg, pb, pm, pv, out);
}